// round 1
// baseline (speedup 1.0000x reference)
#include <cuda_runtime.h>

// ---------------- problem constants ----------------
#define NROWS   32768        // B*BARS*BEATS*FRAC
#define KF      940          // input features (10*2*47)
#define KP      944          // padded K for weight buffer
#define NOUT    100          // linear out
#define NSEQ_B  4096         // beats LSTM sequences (B*BARS*BEATS)
#define NSEQ_R  1024         // bars LSTM sequences (B*BARS)
#define BEATS_OUT_ELEMS (32768 * 16)   // 524288
#define BARS_OUT_OFF    BEATS_OUT_ELEMS

// ---------------- scratch (device globals; no allocation allowed) ----------
__device__ float g_Wp[128 * KP];        // permuted+padded linear weight [128][944]
__device__ float g_gb[64];              // beats LSTM combined gate bias
__device__ float g_Xlin[(size_t)NROWS * NOUT];  // relu(linear) activations
__device__ float g_XG[(size_t)NROWS * 64];      // beats LSTM precomputed input gates

__device__ __forceinline__ float sigmoidf_(float x) {
    return 1.0f / (1.0f + __expf(-x));
}

// ---------------- K0: permute weights + combine beat biases ----------------
// memory index m over [10,2,47]: m = c10*94 + c2*47 + c47
// feature index f over [10,47,2]: f = c10*94 + c47*2 + c2
__global__ void prep_kernel(const float* __restrict__ lin_w,
                            const float* __restrict__ b_bih,
                            const float* __restrict__ b_bhh) {
    int idx = blockIdx.x * blockDim.x + threadIdx.x;
    if (idx < 128 * KP) {
        int o = idx / KP;
        int m = idx % KP;
        float v = 0.0f;
        if (o < NOUT && m < KF) {
            int c10 = m / 94;
            int r   = m % 94;
            int c2  = r / 47;
            int c47 = r % 47;
            int f   = c10 * 94 + c47 * 2 + c2;
            v = lin_w[o * KF + f];
        }
        g_Wp[idx] = v;
    } else if (idx < 128 * KP + 64) {
        int j = idx - 128 * KP;
        g_gb[j] = b_bih[j] + b_bhh[j];
    }
}

// ---------------- K1: Xlin = relu(X @ Wp^T + b) -----------------------------
// block tile: 64 rows x 128 cols (100 valid), BK=16, 256 threads,
// thread tile 4x8, all fp32.
__global__ void gemm1_kernel(const float* __restrict__ X,
                             const float* __restrict__ lin_b) {
    __shared__ float Xs[16][64];
    __shared__ float Ws[16][128];
    const int tid  = threadIdx.x;
    const int tx   = tid & 15;      // 0..15 -> col group (8 cols)
    const int ty   = tid >> 4;      // 0..15 -> row group (4 rows)
    const int row0 = blockIdx.x * 64;
    const int lm   = tid >> 2;      // 0..63  loader row
    const int lk   = (tid & 3) * 4; // 0,4,8,12 loader k offset

    float acc[4][8];
#pragma unroll
    for (int i = 0; i < 4; i++)
#pragma unroll
        for (int j = 0; j < 8; j++) acc[i][j] = 0.0f;

    for (int k0 = 0; k0 < KF; k0 += 16) {
        float4 xa;
        const float* xp = X + (size_t)(row0 + lm) * KF + k0 + lk;
        if (k0 + 16 <= KF) {
            xa = *(const float4*)xp;
        } else {
            xa.x = (k0 + lk + 0 < KF) ? xp[0] : 0.0f;
            xa.y = (k0 + lk + 1 < KF) ? xp[1] : 0.0f;
            xa.z = (k0 + lk + 2 < KF) ? xp[2] : 0.0f;
            xa.w = (k0 + lk + 3 < KF) ? xp[3] : 0.0f;
        }
        float4 wa = *(const float4*)(g_Wp + (size_t)lm * KP + k0 + lk);
        float4 wb = *(const float4*)(g_Wp + (size_t)(lm + 64) * KP + k0 + lk);

        __syncthreads();
        Xs[lk + 0][lm] = xa.x; Xs[lk + 1][lm] = xa.y;
        Xs[lk + 2][lm] = xa.z; Xs[lk + 3][lm] = xa.w;
        Ws[lk + 0][lm] = wa.x; Ws[lk + 1][lm] = wa.y;
        Ws[lk + 2][lm] = wa.z; Ws[lk + 3][lm] = wa.w;
        Ws[lk + 0][lm + 64] = wb.x; Ws[lk + 1][lm + 64] = wb.y;
        Ws[lk + 2][lm + 64] = wb.z; Ws[lk + 3][lm + 64] = wb.w;
        __syncthreads();

#pragma unroll
        for (int kk = 0; kk < 16; kk++) {
            float4 a  = *(const float4*)&Xs[kk][ty * 4];
            float4 b0 = *(const float4*)&Ws[kk][tx * 8];
            float4 b1 = *(const float4*)&Ws[kk][tx * 8 + 4];
            float av[4] = {a.x, a.y, a.z, a.w};
            float bv[8] = {b0.x, b0.y, b0.z, b0.w, b1.x, b1.y, b1.z, b1.w};
#pragma unroll
            for (int mi = 0; mi < 4; mi++)
#pragma unroll
                for (int ni = 0; ni < 8; ni++)
                    acc[mi][ni] = fmaf(av[mi], bv[ni], acc[mi][ni]);
        }
    }

#pragma unroll
    for (int mi = 0; mi < 4; mi++) {
        int r = row0 + ty * 4 + mi;
#pragma unroll
        for (int ni = 0; ni < 8; ni++) {
            int cc = tx * 8 + ni;
            if (cc < NOUT) {
                float v = acc[mi][ni] + lin_b[cc];
                g_Xlin[(size_t)r * NOUT + cc] = fmaxf(v, 0.0f);
            }
        }
    }
}

// ---------------- K2: XG = Xlin @ b_wih^T + (bih+bhh) ----------------------
// block tile 64x64, K=100 in BK=20 chunks, thread tile 4x4.
__global__ void gemm2_kernel(const float* __restrict__ bwih) {
    __shared__ float Xs[20][64];
    __shared__ float Ws[20][64];
    const int tid  = threadIdx.x;
    const int tx   = tid & 15;
    const int ty   = tid >> 4;
    const int row0 = blockIdx.x * 64;
    const int lm   = tid >> 2;
    const int lq   = (tid & 3) * 4;

    float acc[4][4];
#pragma unroll
    for (int i = 0; i < 4; i++)
#pragma unroll
        for (int j = 0; j < 4; j++) acc[i][j] = 0.0f;

    for (int k0 = 0; k0 < 100; k0 += 20) {
        float4 xa = *(const float4*)(g_Xlin + (size_t)(row0 + lm) * 100 + k0 + lq);
        float4 wa = *(const float4*)(bwih + (size_t)lm * 100 + k0 + lq);
        float4 xb, wbv;
        if (tid < 64) {
            xb  = *(const float4*)(g_Xlin + (size_t)(row0 + tid) * 100 + k0 + 16);
            wbv = *(const float4*)(bwih + (size_t)tid * 100 + k0 + 16);
        }
        __syncthreads();
        Xs[lq + 0][lm] = xa.x; Xs[lq + 1][lm] = xa.y;
        Xs[lq + 2][lm] = xa.z; Xs[lq + 3][lm] = xa.w;
        Ws[lq + 0][lm] = wa.x; Ws[lq + 1][lm] = wa.y;
        Ws[lq + 2][lm] = wa.z; Ws[lq + 3][lm] = wa.w;
        if (tid < 64) {
            Xs[16][tid] = xb.x; Xs[17][tid] = xb.y;
            Xs[18][tid] = xb.z; Xs[19][tid] = xb.w;
            Ws[16][tid] = wbv.x; Ws[17][tid] = wbv.y;
            Ws[18][tid] = wbv.z; Ws[19][tid] = wbv.w;
        }
        __syncthreads();

#pragma unroll
        for (int kk = 0; kk < 20; kk++) {
            float4 a = *(const float4*)&Xs[kk][ty * 4];
            float4 b = *(const float4*)&Ws[kk][tx * 4];
            float av[4] = {a.x, a.y, a.z, a.w};
            float bv[4] = {b.x, b.y, b.z, b.w};
#pragma unroll
            for (int mi = 0; mi < 4; mi++)
#pragma unroll
                for (int ni = 0; ni < 4; ni++)
                    acc[mi][ni] = fmaf(av[mi], bv[ni], acc[mi][ni]);
        }
    }

#pragma unroll
    for (int mi = 0; mi < 4; mi++) {
        int r = row0 + ty * 4 + mi;
#pragma unroll
        for (int ni = 0; ni < 4; ni++) {
            int cc = tx * 4 + ni;
            g_XG[(size_t)r * 64 + cc] = acc[mi][ni] + g_gb[cc];
        }
    }
}

// ---------------- K3: beats LSTM, one warp per sequence --------------------
// H=16, T=8. lane l owns gate rows l and l+32.
// lanes 0..15 : i_l (row l)      and g_l (row l+32)
// lanes 16..31: f_{l-16} (row l) and o_{l-16} (row l+32)
__global__ void beats_kernel(const float* __restrict__ whh,
                             float* __restrict__ out) {
    const int warp = (blockIdx.x * blockDim.x + threadIdx.x) >> 5;
    const int lane = threadIdx.x & 31;
    if (warp >= NSEQ_B) return;

    float w0[16], w1[16];
#pragma unroll
    for (int j = 0; j < 16; j++) {
        w0[j] = whh[lane * 16 + j];
        w1[j] = whh[(lane + 32) * 16 + j];
    }

    float h = 0.0f, c = 0.0f;
    const float* xg = g_XG + (size_t)warp * 8 * 64;
    float* ob = out + (size_t)warp * 8 * 16;
    const bool lo = lane < 16;

    for (int t = 0; t < 8; t++) {
        float ga = xg[t * 64 + lane];
        float gb = xg[t * 64 + lane + 32];
#pragma unroll
        for (int j = 0; j < 16; j++) {
            float hj = __shfl_sync(0xffffffffu, h, j);
            ga = fmaf(w0[j], hj, ga);
            gb = fmaf(w1[j], hj, gb);
        }
        float A, Bv;
        if (lo) {
            A  = sigmoidf_(ga) * tanhf(gb);  // sig(i)*tanh(g)
            Bv = 0.0f;
        } else {
            A  = sigmoidf_(ga);              // sig(f)
            Bv = sigmoidf_(gb);              // sig(o)
        }
        float fj = __shfl_sync(0xffffffffu, A,  lane + 16);
        float oj = __shfl_sync(0xffffffffu, Bv, lane + 16);
        if (lo) {
            c = fmaf(fj, c, A);
            h = oj * tanhf(c);
            ob[t * 16 + lane] = h;
        }
    }
}

// ---------------- K4: bars bidirectional LSTM, warp per (seq, dir) ---------
// H=32 -> lane l owns all 4 gates (i,f,g,o) of hidden unit l. T=4, in=16.
__global__ void bars_kernel(const float* __restrict__ f_wih,
                            const float* __restrict__ f_whh,
                            const float* __restrict__ f_bih,
                            const float* __restrict__ f_bhh,
                            const float* __restrict__ r_wih,
                            const float* __restrict__ r_whh,
                            const float* __restrict__ r_bih,
                            const float* __restrict__ r_bhh,
                            float* __restrict__ out) {
    __shared__ float s_wih[16][128];  // [j][gate]
    __shared__ float s_whh[32][128];  // [j][gate]
    __shared__ float s_b[128];

    const int d = blockIdx.y;  // 0=fwd, 1=rev
    const float* wih  = d ? r_wih : f_wih;
    const float* whh  = d ? r_whh : f_whh;
    const float* bihp = d ? r_bih : f_bih;
    const float* bhhp = d ? r_bhh : f_bhh;

    for (int i = threadIdx.x; i < 128 * 16; i += blockDim.x) {
        int g = i >> 4, j = i & 15;
        s_wih[j][g] = wih[i];
    }
    for (int i = threadIdx.x; i < 128 * 32; i += blockDim.x) {
        int g = i >> 5, j = i & 31;
        s_whh[j][g] = whh[i];
    }
    if (threadIdx.x < 128) s_b[threadIdx.x] = bihp[threadIdx.x] + bhhp[threadIdx.x];
    __syncthreads();

    const int warp = threadIdx.x >> 5;
    const int lane = threadIdx.x & 31;
    const int n = blockIdx.x * 8 + warp;  // 0..1023

    const float* beats = out;                 // beats region
    float* bars = out + BARS_OUT_OFF;

    float h = 0.0f, c = 0.0f;
    for (int s = 0; s < 4; s++) {
        int t = d ? (3 - s) : s;
        float xv = 0.0f;
        if (lane < 16)
            xv = beats[(((size_t)n * 4 + t) * 8 + 7) * 16 + lane];

        float gi = s_b[lane];
        float gf = s_b[32 + lane];
        float gg = s_b[64 + lane];
        float go = s_b[96 + lane];
#pragma unroll
        for (int j = 0; j < 16; j++) {
            float xj = __shfl_sync(0xffffffffu, xv, j);
            gi = fmaf(s_wih[j][lane],      xj, gi);
            gf = fmaf(s_wih[j][32 + lane], xj, gf);
            gg = fmaf(s_wih[j][64 + lane], xj, gg);
            go = fmaf(s_wih[j][96 + lane], xj, go);
        }
#pragma unroll
        for (int j = 0; j < 32; j++) {
            float hj = __shfl_sync(0xffffffffu, h, j);
            gi = fmaf(s_whh[j][lane],      hj, gi);
            gf = fmaf(s_whh[j][32 + lane], hj, gf);
            gg = fmaf(s_whh[j][64 + lane], hj, gg);
            go = fmaf(s_whh[j][96 + lane], hj, go);
        }
        c = fmaf(sigmoidf_(gf), c, sigmoidf_(gi) * tanhf(gg));
        h = sigmoidf_(go) * tanhf(c);
        bars[((size_t)n * 4 + t) * 64 + d * 32 + lane] = h;
    }
}

// ---------------- launch ----------------------------------------------------
extern "C" void kernel_launch(void* const* d_in, const int* in_sizes, int n_in,
                              void* d_out, int out_size) {
    const float* channels = (const float*)d_in[0];
    const float* lin_w    = (const float*)d_in[1];
    const float* lin_b    = (const float*)d_in[2];
    const float* b_wih    = (const float*)d_in[3];
    const float* b_whh    = (const float*)d_in[4];
    const float* b_bih    = (const float*)d_in[5];
    const float* b_bhh    = (const float*)d_in[6];
    const float* f_wih    = (const float*)d_in[7];
    const float* f_whh    = (const float*)d_in[8];
    const float* f_bih    = (const float*)d_in[9];
    const float* f_bhh    = (const float*)d_in[10];
    const float* r_wih    = (const float*)d_in[11];
    const float* r_whh    = (const float*)d_in[12];
    const float* r_bih    = (const float*)d_in[13];
    const float* r_bhh    = (const float*)d_in[14];
    float* out = (float*)d_out;

    prep_kernel<<<(128 * KP + 64 + 255) / 256, 256>>>(lin_w, b_bih, b_bhh);
    gemm1_kernel<<<NROWS / 64, 256>>>(channels, lin_b);
    gemm2_kernel<<<NROWS / 64, 256>>>(b_wih);
    beats_kernel<<<NSEQ_B * 32 / 256, 256>>>(b_whh, out);
    dim3 g4(NSEQ_R / 8, 2);
    bars_kernel<<<g4, 256>>>(f_wih, f_whh, f_bih, f_bhh,
                             r_wih, r_whh, r_bih, r_bhh, out);
}

// round 4
// speedup vs baseline: 2.7147x; 2.7147x over previous
#include <cuda_runtime.h>
#include <cuda_bf16.h>
#include <cstdint>

// ---------------- problem constants ----------------
#define NROWS   32768        // B*BARS*BEATS*FRAC
#define KF      940          // input features (10*2*47)
#define KPAD    960          // K padded to 30 x 32
#define NOUT    100          // linear out
#define NSEQ_B  4096         // beats LSTM sequences
#define NSEQ_R  1024         // bars LSTM sequences
#define BEATS_OUT_ELEMS (32768 * 16)
#define BARS_OUT_OFF    BEATS_OUT_ELEMS
#define SSTR    40           // smem row stride in bf16 elems (80B, 16B-aligned)

typedef unsigned int u32;

// ---------------- scratch ----------------
__device__ __nv_bfloat16 g_Whi[128 * KPAD];
__device__ __nv_bfloat16 g_Wlo[128 * KPAD];
__device__ float g_gb[64];
__device__ float g_Xlin[(size_t)NROWS * NOUT];
__device__ float g_XG[(size_t)NROWS * 64];

__device__ __forceinline__ float sigmoidf_(float x) {
    return 1.0f / (1.0f + __expf(-x));
}

// ---------------- K0: permute + split weights, combine biases --------------
__global__ void prep_kernel(const float* __restrict__ lin_w,
                            const float* __restrict__ b_bih,
                            const float* __restrict__ b_bhh) {
    int idx = blockIdx.x * blockDim.x + threadIdx.x;
    if (idx < 128 * KPAD) {
        int o = idx / KPAD;
        int m = idx % KPAD;
        float v = 0.0f;
        if (o < NOUT && m < KF) {
            int c10 = m / 94;
            int r   = m % 94;
            int c2  = r / 47;
            int c47 = r % 47;
            v = lin_w[o * KF + c10 * 94 + c47 * 2 + c2];
        }
        __nv_bfloat16 hi = __float2bfloat16_rn(v);
        g_Whi[idx] = hi;
        g_Wlo[idx] = __float2bfloat16_rn(v - __bfloat162float(hi));
    } else if (idx < 128 * KPAD + 64) {
        int j = idx - 128 * KPAD;
        g_gb[j] = b_bih[j] + b_bhh[j];
    }
}

// ---------------- mma helpers ----------------
__device__ __forceinline__ void ldsm4(u32& r0, u32& r1, u32& r2, u32& r3,
                                      u32 addr) {
    asm volatile("ldmatrix.sync.aligned.m8n8.x4.shared.b16 {%0,%1,%2,%3},[%4];"
                 : "=r"(r0), "=r"(r1), "=r"(r2), "=r"(r3) : "r"(addr));
}
__device__ __forceinline__ void ldsm2(u32& r0, u32& r1, u32 addr) {
    asm volatile("ldmatrix.sync.aligned.m8n8.x2.shared.b16 {%0,%1},[%2];"
                 : "=r"(r0), "=r"(r1) : "r"(addr));
}
__device__ __forceinline__ void mma_bf16(float* c, const u32* a, const u32* b) {
    asm volatile(
        "mma.sync.aligned.m16n8k16.row.col.f32.bf16.bf16.f32 "
        "{%0,%1,%2,%3},{%4,%5,%6,%7},{%8,%9},{%0,%1,%2,%3};"
        : "+f"(c[0]), "+f"(c[1]), "+f"(c[2]), "+f"(c[3])
        : "r"(a[0]), "r"(a[1]), "r"(a[2]), "r"(a[3]), "r"(b[0]), "r"(b[1]));
}

// Register staging for the double-buffer prefetch in gemm1.
struct TileRegs {
    float x[16];
    uint4 wh[2];
    uint4 wl[2];
};

__device__ __forceinline__ void load_tile(int K0, int lc,
                                          const float* __restrict__ xrow,
                                          const __nv_bfloat16* __restrict__ whrow,
                                          const __nv_bfloat16* __restrict__ wlrow,
                                          TileRegs& t) {
#pragma unroll
    for (int j = 0; j < 4; j++) {
        int kb = K0 + lc + j * 4;
        if (kb + 3 < KF) {
            float4 v = *(const float4*)(xrow + K0 + j * 4);
            t.x[j * 4 + 0] = v.x; t.x[j * 4 + 1] = v.y;
            t.x[j * 4 + 2] = v.z; t.x[j * 4 + 3] = v.w;
        } else {
#pragma unroll
            for (int e = 0; e < 4; e++)
                t.x[j * 4 + e] = (kb + e < KF) ? xrow[K0 + j * 4 + e] : 0.0f;
        }
    }
    t.wh[0] = *(const uint4*)(whrow + K0);
    t.wh[1] = *(const uint4*)(whrow + K0 + 8);
    t.wl[0] = *(const uint4*)(wlrow + K0);
    t.wl[1] = *(const uint4*)(wlrow + K0 + 8);
}

// ---------------- K1: Xlin = relu(X @ W^T + b) via 3x bf16 mma -------------
// BM=128, BN=128, BK=32, 256 threads, warp tile 64x32.
__global__ __launch_bounds__(256)
void gemm1_kernel(const float* __restrict__ X, const float* __restrict__ lin_b) {
    __shared__ __align__(16) __nv_bfloat16 sXhi[128 * SSTR];
    __shared__ __align__(16) __nv_bfloat16 sXlo[128 * SSTR];
    __shared__ __align__(16) __nv_bfloat16 sWhi[128 * SSTR];
    __shared__ __align__(16) __nv_bfloat16 sWlo[128 * SSTR];

    const int tid  = threadIdx.x;
    const int row0 = blockIdx.x * 128;
    const int lr   = tid >> 1;        // 0..127 loader row
    const int lc   = (tid & 1) * 16;  // 0 / 16 loader col base

    const float* xrow = X + (size_t)(row0 + lr) * KF + lc;
    const __nv_bfloat16* whrow = g_Whi + lr * KPAD + lc;
    const __nv_bfloat16* wlrow = g_Wlo + lr * KPAD + lc;

    // ldmatrix lane geometry
    const int lane = tid & 31;
    const int w    = tid >> 5;
    const int wm   = w & 1;       // 0..1  -> 64-row half
    const int wn   = w >> 1;      // 0..3  -> 32-col quarter
    const int dra  = ((lane >> 3) & 1) * 8 + (lane & 7);
    const int dca  = (lane >> 4) * 8;
    const int aoff = (wm * 64 + dra) * SSTR + dca;   // + mf*16*SSTR + kf
    const int l2   = lane & 15;
    const int boff = (wn * 32 + (l2 & 7)) * SSTR + (l2 >> 3) * 8;  // + nf*8*SSTR + kf

    const u32 bXhi = (u32)__cvta_generic_to_shared(sXhi);
    const u32 bXlo = (u32)__cvta_generic_to_shared(sXlo);
    const u32 bWhi = (u32)__cvta_generic_to_shared(sWhi);
    const u32 bWlo = (u32)__cvta_generic_to_shared(sWlo);

    float acc[4][4][4];
#pragma unroll
    for (int a = 0; a < 4; a++)
#pragma unroll
        for (int b = 0; b < 4; b++)
#pragma unroll
            for (int c = 0; c < 4; c++) acc[a][b][c] = 0.0f;

    TileRegs t;
    load_tile(0, lc, xrow, whrow, wlrow, t);

    for (int it = 0; it < 30; ++it) {
        if (it) __syncthreads();
        // store prefetched regs -> smem (split X into hi/lo on the fly)
        {
            int off = lr * SSTR + lc;
#pragma unroll
            for (int p = 0; p < 8; p++) {
                float a = t.x[2 * p], b = t.x[2 * p + 1];
                __nv_bfloat162 h, l;
                h.x = __float2bfloat16_rn(a);
                h.y = __float2bfloat16_rn(b);
                l.x = __float2bfloat16_rn(a - __bfloat162float(h.x));
                l.y = __float2bfloat16_rn(b - __bfloat162float(h.y));
                *(__nv_bfloat162*)(sXhi + off + 2 * p) = h;
                *(__nv_bfloat162*)(sXlo + off + 2 * p) = l;
            }
            *(uint4*)(sWhi + off)     = t.wh[0];
            *(uint4*)(sWhi + off + 8) = t.wh[1];
            *(uint4*)(sWlo + off)     = t.wl[0];
            *(uint4*)(sWlo + off + 8) = t.wl[1];
        }
        __syncthreads();
        if (it + 1 < 30) load_tile((it + 1) * 32, lc, xrow, whrow, wlrow, t);

#pragma unroll
        for (int kf = 0; kf < 32; kf += 16) {
            u32 ahi[4][4];
            u32 alo[4][4];
            u32 bhi[4][2];
            u32 blo[4][2];
#pragma unroll
            for (int mf = 0; mf < 4; mf++) {
                u32 ea = (u32)(aoff + mf * 16 * SSTR + kf) * 2u;
                ldsm4(ahi[mf][0], ahi[mf][1], ahi[mf][2], ahi[mf][3], bXhi + ea);
                ldsm4(alo[mf][0], alo[mf][1], alo[mf][2], alo[mf][3], bXlo + ea);
            }
#pragma unroll
            for (int nf = 0; nf < 4; nf++) {
                u32 eb = (u32)(boff + nf * 8 * SSTR + kf) * 2u;
                ldsm2(bhi[nf][0], bhi[nf][1], bWhi + eb);
                ldsm2(blo[nf][0], blo[nf][1], bWlo + eb);
            }
#pragma unroll
            for (int mf = 0; mf < 4; mf++)
#pragma unroll
                for (int nf = 0; nf < 4; nf++) {
                    mma_bf16(acc[mf][nf], ahi[mf], bhi[nf]);
                    mma_bf16(acc[mf][nf], ahi[mf], blo[nf]);
                    mma_bf16(acc[mf][nf], alo[mf], bhi[nf]);
                }
        }
    }

    // epilogue: relu + bias, cols < 100
    const int g  = lane >> 2;
    const int t4 = lane & 3;
#pragma unroll
    for (int mf = 0; mf < 4; mf++)
#pragma unroll
        for (int nf = 0; nf < 4; nf++) {
            int col = wn * 32 + nf * 8 + t4 * 2;
            if (col < NOUT) {
                float b0 = __ldg(lin_b + col), b1 = __ldg(lin_b + col + 1);
                int r1 = row0 + wm * 64 + mf * 16 + g;
                float2 v0, v1;
                v0.x = fmaxf(acc[mf][nf][0] + b0, 0.0f);
                v0.y = fmaxf(acc[mf][nf][1] + b1, 0.0f);
                v1.x = fmaxf(acc[mf][nf][2] + b0, 0.0f);
                v1.y = fmaxf(acc[mf][nf][3] + b1, 0.0f);
                *(float2*)(g_Xlin + (size_t)r1 * NOUT + col) = v0;
                *(float2*)(g_Xlin + (size_t)(r1 + 8) * NOUT + col) = v1;
            }
        }
}

// ---------------- K2: XG = Xlin @ b_wih^T + (bih+bhh) ----------------------
__global__ void gemm2_kernel(const float* __restrict__ bwih) {
    __shared__ float Xs[20][64];
    __shared__ float Ws[20][64];
    const int tid  = threadIdx.x;
    const int tx   = tid & 15;
    const int ty   = tid >> 4;
    const int row0 = blockIdx.x * 64;
    const int lm   = tid >> 2;
    const int lq   = (tid & 3) * 4;

    float acc[4][4];
#pragma unroll
    for (int i = 0; i < 4; i++)
#pragma unroll
        for (int j = 0; j < 4; j++) acc[i][j] = 0.0f;

    for (int k0 = 0; k0 < 100; k0 += 20) {
        float4 xa = *(const float4*)(g_Xlin + (size_t)(row0 + lm) * 100 + k0 + lq);
        float4 wa = *(const float4*)(bwih + (size_t)lm * 100 + k0 + lq);
        float4 xb, wbv;
        if (tid < 64) {
            xb  = *(const float4*)(g_Xlin + (size_t)(row0 + tid) * 100 + k0 + 16);
            wbv = *(const float4*)(bwih + (size_t)tid * 100 + k0 + 16);
        }
        __syncthreads();
        Xs[lq + 0][lm] = xa.x; Xs[lq + 1][lm] = xa.y;
        Xs[lq + 2][lm] = xa.z; Xs[lq + 3][lm] = xa.w;
        Ws[lq + 0][lm] = wa.x; Ws[lq + 1][lm] = wa.y;
        Ws[lq + 2][lm] = wa.z; Ws[lq + 3][lm] = wa.w;
        if (tid < 64) {
            Xs[16][tid] = xb.x; Xs[17][tid] = xb.y;
            Xs[18][tid] = xb.z; Xs[19][tid] = xb.w;
            Ws[16][tid] = wbv.x; Ws[17][tid] = wbv.y;
            Ws[18][tid] = wbv.z; Ws[19][tid] = wbv.w;
        }
        __syncthreads();

#pragma unroll
        for (int kk = 0; kk < 20; kk++) {
            float4 a = *(const float4*)&Xs[kk][ty * 4];
            float4 b = *(const float4*)&Ws[kk][tx * 4];
            float av[4] = {a.x, a.y, a.z, a.w};
            float bv[4] = {b.x, b.y, b.z, b.w};
#pragma unroll
            for (int mi = 0; mi < 4; mi++)
#pragma unroll
                for (int ni = 0; ni < 4; ni++)
                    acc[mi][ni] = fmaf(av[mi], bv[ni], acc[mi][ni]);
        }
    }

#pragma unroll
    for (int mi = 0; mi < 4; mi++) {
        int r = row0 + ty * 4 + mi;
#pragma unroll
        for (int ni = 0; ni < 4; ni++) {
            int cc = tx * 4 + ni;
            g_XG[(size_t)r * 64 + cc] = acc[mi][ni] + g_gb[cc];
        }
    }
}

// ---------------- K3: beats LSTM, one warp per sequence --------------------
__global__ void beats_kernel(const float* __restrict__ whh,
                             float* __restrict__ out) {
    const int warp = (blockIdx.x * blockDim.x + threadIdx.x) >> 5;
    const int lane = threadIdx.x & 31;
    if (warp >= NSEQ_B) return;

    float w0[16], w1[16];
#pragma unroll
    for (int j = 0; j < 16; j++) {
        w0[j] = whh[lane * 16 + j];
        w1[j] = whh[(lane + 32) * 16 + j];
    }

    float h = 0.0f, c = 0.0f;
    const float* xg = g_XG + (size_t)warp * 8 * 64;
    float* ob = out + (size_t)warp * 8 * 16;
    const bool lo = lane < 16;

    for (int t = 0; t < 8; t++) {
        float ga = xg[t * 64 + lane];
        float gb = xg[t * 64 + lane + 32];
#pragma unroll
        for (int j = 0; j < 16; j++) {
            float hj = __shfl_sync(0xffffffffu, h, j);
            ga = fmaf(w0[j], hj, ga);
            gb = fmaf(w1[j], hj, gb);
        }
        float A, Bv;
        if (lo) {
            A  = sigmoidf_(ga) * tanhf(gb);
            Bv = 0.0f;
        } else {
            A  = sigmoidf_(ga);
            Bv = sigmoidf_(gb);
        }
        float fj = __shfl_sync(0xffffffffu, A,  lane + 16);
        float oj = __shfl_sync(0xffffffffu, Bv, lane + 16);
        if (lo) {
            c = fmaf(fj, c, A);
            h = oj * tanhf(c);
            ob[t * 16 + lane] = h;
        }
    }
}

// ---------------- K4: bars bidirectional LSTM ------------------------------
__global__ void bars_kernel(const float* __restrict__ f_wih,
                            const float* __restrict__ f_whh,
                            const float* __restrict__ f_bih,
                            const float* __restrict__ f_bhh,
                            const float* __restrict__ r_wih,
                            const float* __restrict__ r_whh,
                            const float* __restrict__ r_bih,
                            const float* __restrict__ r_bhh,
                            float* __restrict__ out) {
    __shared__ float s_wih[16][128];
    __shared__ float s_whh[32][128];
    __shared__ float s_b[128];

    const int d = blockIdx.y;
    const float* wih  = d ? r_wih : f_wih;
    const float* whh  = d ? r_whh : f_whh;
    const float* bihp = d ? r_bih : f_bih;
    const float* bhhp = d ? r_bhh : f_bhh;

    for (int i = threadIdx.x; i < 128 * 16; i += blockDim.x) {
        int g = i >> 4, j = i & 15;
        s_wih[j][g] = wih[i];
    }
    for (int i = threadIdx.x; i < 128 * 32; i += blockDim.x) {
        int g = i >> 5, j = i & 31;
        s_whh[j][g] = whh[i];
    }
    if (threadIdx.x < 128) s_b[threadIdx.x] = bihp[threadIdx.x] + bhhp[threadIdx.x];
    __syncthreads();

    const int warp = threadIdx.x >> 5;
    const int lane = threadIdx.x & 31;
    const int n = blockIdx.x * 8 + warp;

    const float* beats = out;
    float* bars = out + BARS_OUT_OFF;

    float h = 0.0f, c = 0.0f;
    for (int s = 0; s < 4; s++) {
        int t = d ? (3 - s) : s;
        float xv = 0.0f;
        if (lane < 16)
            xv = beats[(((size_t)n * 4 + t) * 8 + 7) * 16 + lane];

        float gi = s_b[lane];
        float gf = s_b[32 + lane];
        float gg = s_b[64 + lane];
        float go = s_b[96 + lane];
#pragma unroll
        for (int j = 0; j < 16; j++) {
            float xj = __shfl_sync(0xffffffffu, xv, j);
            gi = fmaf(s_wih[j][lane],      xj, gi);
            gf = fmaf(s_wih[j][32 + lane], xj, gf);
            gg = fmaf(s_wih[j][64 + lane], xj, gg);
            go = fmaf(s_wih[j][96 + lane], xj, go);
        }
#pragma unroll
        for (int j = 0; j < 32; j++) {
            float hj = __shfl_sync(0xffffffffu, h, j);
            gi = fmaf(s_whh[j][lane],      hj, gi);
            gf = fmaf(s_whh[j][32 + lane], hj, gf);
            gg = fmaf(s_whh[j][64 + lane], hj, gg);
            go = fmaf(s_whh[j][96 + lane], hj, go);
        }
        c = fmaf(sigmoidf_(gf), c, sigmoidf_(gi) * tanhf(gg));
        h = sigmoidf_(go) * tanhf(c);
        bars[((size_t)n * 4 + t) * 64 + d * 32 + lane] = h;
    }
}

// ---------------- launch ----------------------------------------------------
extern "C" void kernel_launch(void* const* d_in, const int* in_sizes, int n_in,
                              void* d_out, int out_size) {
    const float* channels = (const float*)d_in[0];
    const float* lin_w    = (const float*)d_in[1];
    const float* lin_b    = (const float*)d_in[2];
    const float* b_wih    = (const float*)d_in[3];
    const float* b_whh    = (const float*)d_in[4];
    const float* b_bih    = (const float*)d_in[5];
    const float* b_bhh    = (const float*)d_in[6];
    const float* f_wih    = (const float*)d_in[7];
    const float* f_whh    = (const float*)d_in[8];
    const float* f_bih    = (const float*)d_in[9];
    const float* f_bhh    = (const float*)d_in[10];
    const float* r_wih    = (const float*)d_in[11];
    const float* r_whh    = (const float*)d_in[12];
    const float* r_bih    = (const float*)d_in[13];
    const float* r_bhh    = (const float*)d_in[14];
    float* out = (float*)d_out;

    prep_kernel<<<(128 * KPAD + 64 + 255) / 256, 256>>>(lin_w, b_bih, b_bhh);
    gemm1_kernel<<<NROWS / 128, 256>>>(channels, lin_b);
    gemm2_kernel<<<NROWS / 64, 256>>>(b_wih);
    beats_kernel<<<NSEQ_B * 32 / 256, 256>>>(b_whh, out);
    dim3 g4(NSEQ_R / 8, 2);
    bars_kernel<<<g4, 256>>>(f_wih, f_whh, f_bih, f_bhh,
                             r_wih, r_whh, r_bih, r_bhh, out);
}

// round 5
// speedup vs baseline: 2.7688x; 1.0199x over previous
#include <cuda_runtime.h>
#include <cuda_bf16.h>
#include <cstdint>

// ---------------- problem constants ----------------
#define NROWS   32768        // B*BARS*BEATS*FRAC
#define KF      940          // input features (10*2*47)
#define KPAD    960          // K padded to 30 x 32
#define NOUT    100          // linear out
#define K2PAD   112          // padded K for gemm2 (7 x 16)
#define NSEQ_B  4096         // beats LSTM sequences
#define NSEQ_R  1024         // bars LSTM sequences
#define BEATS_OUT_ELEMS (32768 * 16)
#define BARS_OUT_OFF    BEATS_OUT_ELEMS
#define SSTR    40           // smem row stride in bf16 elems (80B, 16B-aligned)

typedef unsigned int u32;

// ---------------- scratch ----------------
__device__ __nv_bfloat16 g_Whi[128 * KPAD];
__device__ __nv_bfloat16 g_Wlo[128 * KPAD];
__device__ __nv_bfloat16 g_Wbhi[64 * K2PAD];   // beats wih split
__device__ __nv_bfloat16 g_Wblo[64 * K2PAD];
__device__ float g_gb[64];
// Xlin as bf16 hi/lo, row stride K2PAD; pad cols [100,112) never written -> stay 0
__device__ __nv_bfloat16 g_Xhi[(size_t)NROWS * K2PAD];
__device__ __nv_bfloat16 g_Xlo[(size_t)NROWS * K2PAD];
__device__ float g_XG[(size_t)NROWS * 64];

__device__ __forceinline__ float sigmoidf_(float x) {
    return 1.0f / (1.0f + __expf(-x));
}

// ---------------- K0: permute + split weights, combine biases --------------
__global__ void prep_kernel(const float* __restrict__ lin_w,
                            const float* __restrict__ b_wih,
                            const float* __restrict__ b_bih,
                            const float* __restrict__ b_bhh) {
    int idx = blockIdx.x * blockDim.x + threadIdx.x;
    if (idx < 128 * KPAD) {
        int o = idx / KPAD;
        int m = idx % KPAD;
        float v = 0.0f;
        if (o < NOUT && m < KF) {
            int c10 = m / 94;
            int r   = m % 94;
            int c2  = r / 47;
            int c47 = r % 47;
            v = lin_w[o * KF + c10 * 94 + c47 * 2 + c2];
        }
        __nv_bfloat16 hi = __float2bfloat16_rn(v);
        g_Whi[idx] = hi;
        g_Wlo[idx] = __float2bfloat16_rn(v - __bfloat162float(hi));
    } else if (idx < 128 * KPAD + 64 * K2PAD) {
        int j = idx - 128 * KPAD;
        int n = j / K2PAD;
        int k = j % K2PAD;
        float v = (k < NOUT) ? b_wih[n * NOUT + k] : 0.0f;
        __nv_bfloat16 hi = __float2bfloat16_rn(v);
        g_Wbhi[j] = hi;
        g_Wblo[j] = __float2bfloat16_rn(v - __bfloat162float(hi));
    } else if (idx < 128 * KPAD + 64 * K2PAD + 64) {
        int j = idx - 128 * KPAD - 64 * K2PAD;
        g_gb[j] = b_bih[j] + b_bhh[j];
    }
}

// ---------------- mma helpers ----------------
__device__ __forceinline__ void ldsm4(u32& r0, u32& r1, u32& r2, u32& r3,
                                      u32 addr) {
    asm volatile("ldmatrix.sync.aligned.m8n8.x4.shared.b16 {%0,%1,%2,%3},[%4];"
                 : "=r"(r0), "=r"(r1), "=r"(r2), "=r"(r3) : "r"(addr));
}
__device__ __forceinline__ void ldsm2(u32& r0, u32& r1, u32 addr) {
    asm volatile("ldmatrix.sync.aligned.m8n8.x2.shared.b16 {%0,%1},[%2];"
                 : "=r"(r0), "=r"(r1) : "r"(addr));
}
__device__ __forceinline__ void mma_bf16(float* c, const u32* a, const u32* b) {
    asm volatile(
        "mma.sync.aligned.m16n8k16.row.col.f32.bf16.bf16.f32 "
        "{%0,%1,%2,%3},{%4,%5,%6,%7},{%8,%9},{%0,%1,%2,%3};"
        : "+f"(c[0]), "+f"(c[1]), "+f"(c[2]), "+f"(c[3])
        : "r"(a[0]), "r"(a[1]), "r"(a[2]), "r"(a[3]), "r"(b[0]), "r"(b[1]));
}

// Register staging for the double-buffer prefetch in gemm1.
struct TileRegs {
    float x[16];
    uint4 wh[2];
    uint4 wl[2];
};

__device__ __forceinline__ void load_tile(int K0, int lc,
                                          const float* __restrict__ xrow,
                                          const __nv_bfloat16* __restrict__ whrow,
                                          const __nv_bfloat16* __restrict__ wlrow,
                                          TileRegs& t) {
#pragma unroll
    for (int j = 0; j < 4; j++) {
        int kb = K0 + lc + j * 4;
        if (kb + 3 < KF) {
            float4 v = *(const float4*)(xrow + K0 + j * 4);
            t.x[j * 4 + 0] = v.x; t.x[j * 4 + 1] = v.y;
            t.x[j * 4 + 2] = v.z; t.x[j * 4 + 3] = v.w;
        } else {
#pragma unroll
            for (int e = 0; e < 4; e++)
                t.x[j * 4 + e] = (kb + e < KF) ? xrow[K0 + j * 4 + e] : 0.0f;
        }
    }
    t.wh[0] = *(const uint4*)(whrow + K0);
    t.wh[1] = *(const uint4*)(whrow + K0 + 8);
    t.wl[0] = *(const uint4*)(wlrow + K0);
    t.wl[1] = *(const uint4*)(wlrow + K0 + 8);
}

// ---------------- K1: Xlin = relu(X @ W^T + b) via 3x bf16 mma -------------
// BM=128, BN=128, BK=32, 256 threads, warp tile 64x32.
// Epilogue writes bf16 hi/lo split of Xlin to g_Xhi/g_Xlo (stride K2PAD).
__global__ __launch_bounds__(256)
void gemm1_kernel(const float* __restrict__ X, const float* __restrict__ lin_b) {
    __shared__ __align__(16) __nv_bfloat16 sXhi[128 * SSTR];
    __shared__ __align__(16) __nv_bfloat16 sXlo[128 * SSTR];
    __shared__ __align__(16) __nv_bfloat16 sWhi[128 * SSTR];
    __shared__ __align__(16) __nv_bfloat16 sWlo[128 * SSTR];

    const int tid  = threadIdx.x;
    const int row0 = blockIdx.x * 128;
    const int lr   = tid >> 1;        // 0..127 loader row
    const int lc   = (tid & 1) * 16;  // 0 / 16 loader col base

    const float* xrow = X + (size_t)(row0 + lr) * KF + lc;
    const __nv_bfloat16* whrow = g_Whi + lr * KPAD + lc;
    const __nv_bfloat16* wlrow = g_Wlo + lr * KPAD + lc;

    // ldmatrix lane geometry
    const int lane = tid & 31;
    const int w    = tid >> 5;
    const int wm   = w & 1;       // 0..1  -> 64-row half
    const int wn   = w >> 1;      // 0..3  -> 32-col quarter
    const int dra  = ((lane >> 3) & 1) * 8 + (lane & 7);
    const int dca  = (lane >> 4) * 8;
    const int aoff = (wm * 64 + dra) * SSTR + dca;   // + mf*16*SSTR + kf
    const int l2   = lane & 15;
    const int boff = (wn * 32 + (l2 & 7)) * SSTR + (l2 >> 3) * 8;  // + nf*8*SSTR + kf

    const u32 bXhi = (u32)__cvta_generic_to_shared(sXhi);
    const u32 bXlo = (u32)__cvta_generic_to_shared(sXlo);
    const u32 bWhi = (u32)__cvta_generic_to_shared(sWhi);
    const u32 bWlo = (u32)__cvta_generic_to_shared(sWlo);

    float acc[4][4][4];
#pragma unroll
    for (int a = 0; a < 4; a++)
#pragma unroll
        for (int b = 0; b < 4; b++)
#pragma unroll
            for (int c = 0; c < 4; c++) acc[a][b][c] = 0.0f;

    TileRegs t;
    load_tile(0, lc, xrow, whrow, wlrow, t);

    for (int it = 0; it < 30; ++it) {
        if (it) __syncthreads();
        // store prefetched regs -> smem (split X into hi/lo on the fly)
        {
            int off = lr * SSTR + lc;
#pragma unroll
            for (int p = 0; p < 8; p++) {
                float a = t.x[2 * p], b = t.x[2 * p + 1];
                __nv_bfloat162 h, l;
                h.x = __float2bfloat16_rn(a);
                h.y = __float2bfloat16_rn(b);
                l.x = __float2bfloat16_rn(a - __bfloat162float(h.x));
                l.y = __float2bfloat16_rn(b - __bfloat162float(h.y));
                *(__nv_bfloat162*)(sXhi + off + 2 * p) = h;
                *(__nv_bfloat162*)(sXlo + off + 2 * p) = l;
            }
            *(uint4*)(sWhi + off)     = t.wh[0];
            *(uint4*)(sWhi + off + 8) = t.wh[1];
            *(uint4*)(sWlo + off)     = t.wl[0];
            *(uint4*)(sWlo + off + 8) = t.wl[1];
        }
        __syncthreads();
        if (it + 1 < 30) load_tile((it + 1) * 32, lc, xrow, whrow, wlrow, t);

#pragma unroll
        for (int kf = 0; kf < 32; kf += 16) {
            u32 ahi[4][4];
            u32 alo[4][4];
            u32 bhi[4][2];
            u32 blo[4][2];
#pragma unroll
            for (int mf = 0; mf < 4; mf++) {
                u32 ea = (u32)(aoff + mf * 16 * SSTR + kf) * 2u;
                ldsm4(ahi[mf][0], ahi[mf][1], ahi[mf][2], ahi[mf][3], bXhi + ea);
                ldsm4(alo[mf][0], alo[mf][1], alo[mf][2], alo[mf][3], bXlo + ea);
            }
#pragma unroll
            for (int nf = 0; nf < 4; nf++) {
                u32 eb = (u32)(boff + nf * 8 * SSTR + kf) * 2u;
                ldsm2(bhi[nf][0], bhi[nf][1], bWhi + eb);
                ldsm2(blo[nf][0], blo[nf][1], bWlo + eb);
            }
#pragma unroll
            for (int mf = 0; mf < 4; mf++)
#pragma unroll
                for (int nf = 0; nf < 4; nf++) {
                    mma_bf16(acc[mf][nf], ahi[mf], bhi[nf]);
                    mma_bf16(acc[mf][nf], ahi[mf], blo[nf]);
                    mma_bf16(acc[mf][nf], alo[mf], bhi[nf]);
                }
        }
    }

    // epilogue: relu + bias, split to bf16 hi/lo, cols < 100
    const int g  = lane >> 2;
    const int t4 = lane & 3;
#pragma unroll
    for (int mf = 0; mf < 4; mf++)
#pragma unroll
        for (int nf = 0; nf < 4; nf++) {
            int col = wn * 32 + nf * 8 + t4 * 2;
            if (col < NOUT) {
                float b0 = __ldg(lin_b + col), b1 = __ldg(lin_b + col + 1);
                int r1 = row0 + wm * 64 + mf * 16 + g;
                float v0 = fmaxf(acc[mf][nf][0] + b0, 0.0f);
                float v1 = fmaxf(acc[mf][nf][1] + b1, 0.0f);
                float v2 = fmaxf(acc[mf][nf][2] + b0, 0.0f);
                float v3 = fmaxf(acc[mf][nf][3] + b1, 0.0f);
                __nv_bfloat162 h0, l0, h1, l1;
                h0.x = __float2bfloat16_rn(v0);
                h0.y = __float2bfloat16_rn(v1);
                l0.x = __float2bfloat16_rn(v0 - __bfloat162float(h0.x));
                l0.y = __float2bfloat16_rn(v1 - __bfloat162float(h0.y));
                h1.x = __float2bfloat16_rn(v2);
                h1.y = __float2bfloat16_rn(v3);
                l1.x = __float2bfloat16_rn(v2 - __bfloat162float(h1.x));
                l1.y = __float2bfloat16_rn(v3 - __bfloat162float(h1.y));
                *(__nv_bfloat162*)(g_Xhi + (size_t)r1 * K2PAD + col) = h0;
                *(__nv_bfloat162*)(g_Xlo + (size_t)r1 * K2PAD + col) = l0;
                *(__nv_bfloat162*)(g_Xhi + (size_t)(r1 + 8) * K2PAD + col) = h1;
                *(__nv_bfloat162*)(g_Xlo + (size_t)(r1 + 8) * K2PAD + col) = l1;
            }
        }
}

// ---------------- K2: XG = Xlin @ b_wih^T + (bih+bhh) via bf16 mma ---------
// Tile 128x64, K=112 (7 chunks). 8 warps: wm=w&3 (32 rows, mf=2),
// wn=w>>2 (32 cols, nf=4). Fragments loaded directly from global (4B each).
__global__ __launch_bounds__(256)
void gemm2_kernel() {
    const int tid  = threadIdx.x;
    const int lane = tid & 31;
    const int w    = tid >> 5;
    const int wm   = w & 3;
    const int wn   = w >> 2;
    const int g    = lane >> 2;
    const int t4   = lane & 3;
    const int row0 = blockIdx.x * 128 + wm * 32;

    float acc[2][4][4];
#pragma unroll
    for (int a = 0; a < 2; a++)
#pragma unroll
        for (int b = 0; b < 4; b++)
#pragma unroll
            for (int c = 0; c < 4; c++) acc[a][b][c] = 0.0f;

#pragma unroll
    for (int kc = 0; kc < 7; kc++) {
        const int k0 = kc * 16 + t4 * 2;
        u32 ah[2][4], al[2][4], bh[4][2], bl[4][2];
#pragma unroll
        for (int mf = 0; mf < 2; mf++) {
            size_t base = (size_t)(row0 + mf * 16 + g) * K2PAD + k0;
            ah[mf][0] = *(const u32*)(g_Xhi + base);
            ah[mf][1] = *(const u32*)(g_Xhi + base + 8 * K2PAD);
            ah[mf][2] = *(const u32*)(g_Xhi + base + 8);
            ah[mf][3] = *(const u32*)(g_Xhi + base + 8 * K2PAD + 8);
            al[mf][0] = *(const u32*)(g_Xlo + base);
            al[mf][1] = *(const u32*)(g_Xlo + base + 8 * K2PAD);
            al[mf][2] = *(const u32*)(g_Xlo + base + 8);
            al[mf][3] = *(const u32*)(g_Xlo + base + 8 * K2PAD + 8);
        }
#pragma unroll
        for (int nf = 0; nf < 4; nf++) {
            int nbase = (wn * 32 + nf * 8 + g) * K2PAD + k0;
            bh[nf][0] = *(const u32*)(g_Wbhi + nbase);
            bh[nf][1] = *(const u32*)(g_Wbhi + nbase + 8);
            bl[nf][0] = *(const u32*)(g_Wblo + nbase);
            bl[nf][1] = *(const u32*)(g_Wblo + nbase + 8);
        }
#pragma unroll
        for (int mf = 0; mf < 2; mf++)
#pragma unroll
            for (int nf = 0; nf < 4; nf++) {
                mma_bf16(acc[mf][nf], ah[mf], bh[nf]);
                mma_bf16(acc[mf][nf], ah[mf], bl[nf]);
                mma_bf16(acc[mf][nf], al[mf], bh[nf]);
            }
    }

#pragma unroll
    for (int mf = 0; mf < 2; mf++)
#pragma unroll
        for (int nf = 0; nf < 4; nf++) {
            int col = wn * 32 + nf * 8 + t4 * 2;
            float b0 = g_gb[col], b1 = g_gb[col + 1];
            int r = row0 + mf * 16 + g;
            float2 v0, v1;
            v0.x = acc[mf][nf][0] + b0;
            v0.y = acc[mf][nf][1] + b1;
            v1.x = acc[mf][nf][2] + b0;
            v1.y = acc[mf][nf][3] + b1;
            *(float2*)(g_XG + (size_t)r * 64 + col) = v0;
            *(float2*)(g_XG + (size_t)(r + 8) * 64 + col) = v1;
        }
}

// ---------------- K3: beats LSTM, TWO sequences per warp -------------------
// Seq A uses native lane roles, seq B uses xor-16 roles. H=16, T=8.
__global__ __launch_bounds__(256)
void beats_kernel(const float* __restrict__ whh, float* __restrict__ out) {
    const int warp = (blockIdx.x * blockDim.x + threadIdx.x) >> 5;
    const int lane = threadIdx.x & 31;
    if (warp >= NSEQ_B / 2) return;
    const int s0 = warp * 2;
    const int lx = lane ^ 16;

    float wA0[16], wA1[16], wB0[16], wB1[16];
#pragma unroll
    for (int j = 0; j < 16; j++) {
        wA0[j] = whh[lane * 16 + j];
        wA1[j] = whh[(lane + 32) * 16 + j];
        wB0[j] = whh[lx * 16 + j];
        wB1[j] = whh[(lx + 32) * 16 + j];
    }

    float h = 0.0f;          // hA on lanes<16, hB on lanes>=16
    float cA = 0.0f, cB = 0.0f;   // only the owning half uses each
    const float* xgA = g_XG + (size_t)s0 * 512;
    const float* xgB = xgA + 512;
    float* obA = out + (size_t)s0 * 128;
    float* obB = obA + 128;
    const bool loHalf = lane < 16;

    for (int t = 0; t < 8; t++) {
        float gaA = xgA[t * 64 + lane];
        float gbA = xgA[t * 64 + lane + 32];
        float gaB = xgB[t * 64 + lx];
        float gbB = xgB[t * 64 + lx + 32];
#pragma unroll
        for (int j = 0; j < 16; j++) {
            float hAj = __shfl_sync(0xffffffffu, h, j);
            float hBj = __shfl_sync(0xffffffffu, h, 16 + j);
            gaA = fmaf(wA0[j], hAj, gaA);
            gbA = fmaf(wA1[j], hAj, gbA);
            gaB = fmaf(wB0[j], hBj, gaB);
            gbB = fmaf(wB1[j], hBj, gbB);
        }
        // lanes<16:  A-role = (i,g)  -> m-term;  B-role = (f,o)
        // lanes>=16: A-role = (f,o);             B-role = (i,g) -> m-term
        float m, fv, ov;
        if (loHalf) {
            m  = sigmoidf_(gaA) * tanhf(gbA);   // A candidate (local)
            fv = sigmoidf_(gaB);                // B forget (for partner)
            ov = sigmoidf_(gbB);                // B output (for partner)
        } else {
            m  = sigmoidf_(gaB) * tanhf(gbB);   // B candidate (local)
            fv = sigmoidf_(gaA);                // A forget (for partner)
            ov = sigmoidf_(gbA);                // A output (for partner)
        }
        float f = __shfl_xor_sync(0xffffffffu, fv, 16);
        float o = __shfl_xor_sync(0xffffffffu, ov, 16);
        if (loHalf) {
            cA = fmaf(f, cA, m);
            h  = o * tanhf(cA);
            obA[t * 16 + lane] = h;
        } else {
            cB = fmaf(f, cB, m);
            h  = o * tanhf(cB);
            obB[t * 16 + lx] = h;
        }
    }
}

// ---------------- K4: bars bidirectional LSTM ------------------------------
__global__ void bars_kernel(const float* __restrict__ f_wih,
                            const float* __restrict__ f_whh,
                            const float* __restrict__ f_bih,
                            const float* __restrict__ f_bhh,
                            const float* __restrict__ r_wih,
                            const float* __restrict__ r_whh,
                            const float* __restrict__ r_bih,
                            const float* __restrict__ r_bhh,
                            float* __restrict__ out) {
    __shared__ float s_wih[16][128];
    __shared__ float s_whh[32][128];
    __shared__ float s_b[128];

    const int d = blockIdx.y;
    const float* wih  = d ? r_wih : f_wih;
    const float* whh  = d ? r_whh : f_whh;
    const float* bihp = d ? r_bih : f_bih;
    const float* bhhp = d ? r_bhh : f_bhh;

    for (int i = threadIdx.x; i < 128 * 16; i += blockDim.x) {
        int g = i >> 4, j = i & 15;
        s_wih[j][g] = wih[i];
    }
    for (int i = threadIdx.x; i < 128 * 32; i += blockDim.x) {
        int g = i >> 5, j = i & 31;
        s_whh[j][g] = whh[i];
    }
    if (threadIdx.x < 128) s_b[threadIdx.x] = bihp[threadIdx.x] + bhhp[threadIdx.x];
    __syncthreads();

    const int warp = threadIdx.x >> 5;
    const int lane = threadIdx.x & 31;
    const int n = blockIdx.x * 8 + warp;

    const float* beats = out;
    float* bars = out + BARS_OUT_OFF;

    float h = 0.0f, c = 0.0f;
    for (int s = 0; s < 4; s++) {
        int t = d ? (3 - s) : s;
        float xv = 0.0f;
        if (lane < 16)
            xv = beats[(((size_t)n * 4 + t) * 8 + 7) * 16 + lane];

        float gi = s_b[lane];
        float gf = s_b[32 + lane];
        float gg = s_b[64 + lane];
        float go = s_b[96 + lane];
#pragma unroll
        for (int j = 0; j < 16; j++) {
            float xj = __shfl_sync(0xffffffffu, xv, j);
            gi = fmaf(s_wih[j][lane],      xj, gi);
            gf = fmaf(s_wih[j][32 + lane], xj, gf);
            gg = fmaf(s_wih[j][64 + lane], xj, gg);
            go = fmaf(s_wih[j][96 + lane], xj, go);
        }
#pragma unroll
        for (int j = 0; j < 32; j++) {
            float hj = __shfl_sync(0xffffffffu, h, j);
            gi = fmaf(s_whh[j][lane],      hj, gi);
            gf = fmaf(s_whh[j][32 + lane], hj, gf);
            gg = fmaf(s_whh[j][64 + lane], hj, gg);
            go = fmaf(s_whh[j][96 + lane], hj, go);
        }
        c = fmaf(sigmoidf_(gf), c, sigmoidf_(gi) * tanhf(gg));
        h = sigmoidf_(go) * tanhf(c);
        bars[((size_t)n * 4 + t) * 64 + d * 32 + lane] = h;
    }
}

// ---------------- launch ----------------------------------------------------
extern "C" void kernel_launch(void* const* d_in, const int* in_sizes, int n_in,
                              void* d_out, int out_size) {
    const float* channels = (const float*)d_in[0];
    const float* lin_w    = (const float*)d_in[1];
    const float* lin_b    = (const float*)d_in[2];
    const float* b_wih    = (const float*)d_in[3];
    const float* b_whh    = (const float*)d_in[4];
    const float* b_bih    = (const float*)d_in[5];
    const float* b_bhh    = (const float*)d_in[6];
    const float* f_wih    = (const float*)d_in[7];
    const float* f_whh    = (const float*)d_in[8];
    const float* f_bih    = (const float*)d_in[9];
    const float* f_bhh    = (const float*)d_in[10];
    const float* r_wih    = (const float*)d_in[11];
    const float* r_whh    = (const float*)d_in[12];
    const float* r_bih    = (const float*)d_in[13];
    const float* r_bhh    = (const float*)d_in[14];
    float* out = (float*)d_out;

    int prep_n = 128 * KPAD + 64 * K2PAD + 64;
    prep_kernel<<<(prep_n + 255) / 256, 256>>>(lin_w, b_wih, b_bih, b_bhh);
    gemm1_kernel<<<NROWS / 128, 256>>>(channels, lin_b);
    gemm2_kernel<<<NROWS / 128, 256>>>();
    beats_kernel<<<(NSEQ_B / 2) * 32 / 256, 256>>>(b_whh, out);
    dim3 g4(NSEQ_R / 8, 2);
    bars_kernel<<<g4, 256>>>(f_wih, f_whh, f_bih, f_bhh,
                             r_wih, r_whh, r_bih, r_bhh, out);
}

// round 6
// speedup vs baseline: 2.9954x; 1.0818x over previous
#include <cuda_runtime.h>
#include <cuda_bf16.h>
#include <cstdint>

// ---------------- problem constants ----------------
#define NROWS   32768        // B*BARS*BEATS*FRAC
#define KF      940          // input features (10*2*47)
#define KPAD    960          // K padded to 30 x 32
#define NOUT    100          // linear out
#define K2PAD   112          // padded K for gemm2 (7 x 16)
#define NSEQ_B  4096         // beats LSTM sequences
#define NSEQ_R  1024         // bars LSTM sequences
#define BEATS_OUT_ELEMS (32768 * 16)
#define BARS_OUT_OFF    BEATS_OUT_ELEMS
#define SSTR    40           // smem row stride in bf16 elems (80B, 16B-aligned)

// gemm1 double-buffer smem layout (elements / bytes)
#define ARR_ELEMS   (128 * SSTR)          // 5120 elems per array
#define BUF_ELEMS   (4 * ARR_ELEMS)       // 20480 elems per buffer
#define BUF_BYTES   (BUF_ELEMS * 2)       // 40960 B
#define SMEM_TOTAL  (2 * BUF_BYTES)       // 81920 B
#define AXHI 0
#define AXLO (ARR_ELEMS * 2)
#define AWHI (2 * ARR_ELEMS * 2)
#define AWLO (3 * ARR_ELEMS * 2)

typedef unsigned int u32;

// ---------------- scratch ----------------
__device__ __nv_bfloat16 g_Whi[128 * KPAD];
__device__ __nv_bfloat16 g_Wlo[128 * KPAD];
__device__ __nv_bfloat16 g_Wbhi[64 * K2PAD];   // beats wih split
__device__ __nv_bfloat16 g_Wblo[64 * K2PAD];
__device__ float g_gb[64];
// Xlin as bf16 hi/lo, row stride K2PAD; pad cols [100,112) never written -> stay 0
__device__ __nv_bfloat16 g_Xhi[(size_t)NROWS * K2PAD];
__device__ __nv_bfloat16 g_Xlo[(size_t)NROWS * K2PAD];
__device__ float g_XG[(size_t)NROWS * 64];

// ---------------- fast activations ----------------
__device__ __forceinline__ float tanha_(float x) {
    float y;
    asm("tanh.approx.f32 %0, %1;" : "=f"(y) : "f"(x));
    return y;
}
__device__ __forceinline__ float sig_(float x) {
    return fmaf(tanha_(0.5f * x), 0.5f, 0.5f);
}

// ---------------- K0: permute + split weights, combine biases --------------
__global__ void prep_kernel(const float* __restrict__ lin_w,
                            const float* __restrict__ b_wih,
                            const float* __restrict__ b_bih,
                            const float* __restrict__ b_bhh) {
    int idx = blockIdx.x * blockDim.x + threadIdx.x;
    if (idx < 128 * KPAD) {
        int o = idx / KPAD;
        int m = idx % KPAD;
        float v = 0.0f;
        if (o < NOUT && m < KF) {
            int c10 = m / 94;
            int r   = m % 94;
            int c2  = r / 47;
            int c47 = r % 47;
            v = lin_w[o * KF + c10 * 94 + c47 * 2 + c2];
        }
        __nv_bfloat16 hi = __float2bfloat16_rn(v);
        g_Whi[idx] = hi;
        g_Wlo[idx] = __float2bfloat16_rn(v - __bfloat162float(hi));
    } else if (idx < 128 * KPAD + 64 * K2PAD) {
        int j = idx - 128 * KPAD;
        int n = j / K2PAD;
        int k = j % K2PAD;
        float v = (k < NOUT) ? b_wih[n * NOUT + k] : 0.0f;
        __nv_bfloat16 hi = __float2bfloat16_rn(v);
        g_Wbhi[j] = hi;
        g_Wblo[j] = __float2bfloat16_rn(v - __bfloat162float(hi));
    } else if (idx < 128 * KPAD + 64 * K2PAD + 64) {
        int j = idx - 128 * KPAD - 64 * K2PAD;
        g_gb[j] = b_bih[j] + b_bhh[j];
    }
}

// ---------------- mma helpers ----------------
__device__ __forceinline__ void ldsm4(u32& r0, u32& r1, u32& r2, u32& r3,
                                      u32 addr) {
    asm volatile("ldmatrix.sync.aligned.m8n8.x4.shared.b16 {%0,%1,%2,%3},[%4];"
                 : "=r"(r0), "=r"(r1), "=r"(r2), "=r"(r3) : "r"(addr));
}
__device__ __forceinline__ void ldsm2(u32& r0, u32& r1, u32 addr) {
    asm volatile("ldmatrix.sync.aligned.m8n8.x2.shared.b16 {%0,%1},[%2];"
                 : "=r"(r0), "=r"(r1) : "r"(addr));
}
__device__ __forceinline__ void mma_bf16(float* c, const u32* a, const u32* b) {
    asm volatile(
        "mma.sync.aligned.m16n8k16.row.col.f32.bf16.bf16.f32 "
        "{%0,%1,%2,%3},{%4,%5,%6,%7},{%8,%9},{%0,%1,%2,%3};"
        : "+f"(c[0]), "+f"(c[1]), "+f"(c[2]), "+f"(c[3])
        : "r"(a[0]), "r"(a[1]), "r"(a[2]), "r"(a[3]), "r"(b[0]), "r"(b[1]));
}

// Register staging for the double-buffer prefetch in gemm1.
struct TileRegs {
    float x[16];
    uint4 wh[2];
    uint4 wl[2];
};

__device__ __forceinline__ void load_tile(int K0, int lc,
                                          const float* __restrict__ xrow,
                                          const __nv_bfloat16* __restrict__ whrow,
                                          const __nv_bfloat16* __restrict__ wlrow,
                                          TileRegs& t) {
#pragma unroll
    for (int j = 0; j < 4; j++) {
        int kb = K0 + lc + j * 4;
        if (kb + 3 < KF) {
            float4 v = *(const float4*)(xrow + K0 + j * 4);
            t.x[j * 4 + 0] = v.x; t.x[j * 4 + 1] = v.y;
            t.x[j * 4 + 2] = v.z; t.x[j * 4 + 3] = v.w;
        } else {
#pragma unroll
            for (int e = 0; e < 4; e++)
                t.x[j * 4 + e] = (kb + e < KF) ? xrow[K0 + j * 4 + e] : 0.0f;
        }
    }
    t.wh[0] = *(const uint4*)(whrow + K0);
    t.wh[1] = *(const uint4*)(whrow + K0 + 8);
    t.wl[0] = *(const uint4*)(wlrow + K0);
    t.wl[1] = *(const uint4*)(wlrow + K0 + 8);
}

__device__ __forceinline__ void store_tile(__nv_bfloat16* bufbase, int off,
                                           const TileRegs& t) {
    __nv_bfloat16* xh = bufbase + off;
    __nv_bfloat16* xl = bufbase + ARR_ELEMS + off;
    __nv_bfloat16* wh = bufbase + 2 * ARR_ELEMS + off;
    __nv_bfloat16* wl = bufbase + 3 * ARR_ELEMS + off;
#pragma unroll
    for (int p = 0; p < 8; p++) {
        float a = t.x[2 * p], b = t.x[2 * p + 1];
        __nv_bfloat162 h, l;
        h.x = __float2bfloat16_rn(a);
        h.y = __float2bfloat16_rn(b);
        l.x = __float2bfloat16_rn(a - __bfloat162float(h.x));
        l.y = __float2bfloat16_rn(b - __bfloat162float(h.y));
        *(__nv_bfloat162*)(xh + 2 * p) = h;
        *(__nv_bfloat162*)(xl + 2 * p) = l;
    }
    *(uint4*)wh       = t.wh[0];
    *(uint4*)(wh + 8) = t.wh[1];
    *(uint4*)wl       = t.wl[0];
    *(uint4*)(wl + 8) = t.wl[1];
}

// ---------------- K1: Xlin = relu(X @ W^T + b) via 3x bf16 mma -------------
// BM=128, BN=128, BK=32, 256 threads, warp tile 64x32, double-buffered smem.
__global__ __launch_bounds__(256)
void gemm1_kernel(const float* __restrict__ X, const float* __restrict__ lin_b) {
    extern __shared__ __align__(16) __nv_bfloat16 smem[];

    const int tid  = threadIdx.x;
    const int row0 = blockIdx.x * 128;
    const int lr   = tid >> 1;        // 0..127 loader row
    const int lc   = (tid & 1) * 16;  // 0 / 16 loader col base
    const int soff = lr * SSTR + lc;

    const float* xrow = X + (size_t)(row0 + lr) * KF + lc;
    const __nv_bfloat16* whrow = g_Whi + lr * KPAD + lc;
    const __nv_bfloat16* wlrow = g_Wlo + lr * KPAD + lc;

    // ldmatrix lane geometry
    const int lane = tid & 31;
    const int w    = tid >> 5;
    const int wm   = w & 1;       // 0..1  -> 64-row half
    const int wn   = w >> 1;      // 0..3  -> 32-col quarter
    const int dra  = ((lane >> 3) & 1) * 8 + (lane & 7);
    const int dca  = (lane >> 4) * 8;
    const int aoff = (wm * 64 + dra) * SSTR + dca;   // + mf*16*SSTR + kf
    const int l2   = lane & 15;
    const int boff = (wn * 32 + (l2 & 7)) * SSTR + (l2 >> 3) * 8;  // + nf*8*SSTR + kf

    const u32 sbase = (u32)__cvta_generic_to_shared(smem);

    float acc[4][4][4];
#pragma unroll
    for (int a = 0; a < 4; a++)
#pragma unroll
        for (int b = 0; b < 4; b++)
#pragma unroll
            for (int c = 0; c < 4; c++) acc[a][b][c] = 0.0f;

    TileRegs t;
    load_tile(0, lc, xrow, whrow, wlrow, t);
    store_tile(smem, soff, t);                // buffer 0
    load_tile(32, lc, xrow, whrow, wlrow, t); // tile 1 staged in regs
    __syncthreads();

    for (int it = 0; it < 30; ++it) {
        const u32 cb = sbase + (u32)((it & 1) * BUF_BYTES);

#pragma unroll
        for (int kf = 0; kf < 32; kf += 16) {
            u32 ahi[4][4];
            u32 alo[4][4];
            u32 bhi[4][2];
            u32 blo[4][2];
#pragma unroll
            for (int mf = 0; mf < 4; mf++) {
                u32 ea = (u32)(aoff + mf * 16 * SSTR + kf) * 2u;
                ldsm4(ahi[mf][0], ahi[mf][1], ahi[mf][2], ahi[mf][3],
                      cb + AXHI + ea);
                ldsm4(alo[mf][0], alo[mf][1], alo[mf][2], alo[mf][3],
                      cb + AXLO + ea);
            }
#pragma unroll
            for (int nf = 0; nf < 4; nf++) {
                u32 eb = (u32)(boff + nf * 8 * SSTR + kf) * 2u;
                ldsm2(bhi[nf][0], bhi[nf][1], cb + AWHI + eb);
                ldsm2(blo[nf][0], blo[nf][1], cb + AWLO + eb);
            }
#pragma unroll
            for (int mf = 0; mf < 4; mf++)
#pragma unroll
                for (int nf = 0; nf < 4; nf++) {
                    mma_bf16(acc[mf][nf], ahi[mf], bhi[nf]);
                    mma_bf16(acc[mf][nf], ahi[mf], blo[nf]);
                    mma_bf16(acc[mf][nf], alo[mf], bhi[nf]);
                }
        }

        if (it + 1 < 30) {
            // store staged tile it+1 into the other buffer (no race: all warps
            // are past compute(it-1) due to the previous sync)
            store_tile(smem + ((it + 1) & 1) * BUF_ELEMS, soff, t);
            if (it + 2 < 30) load_tile((it + 2) * 32, lc, xrow, whrow, wlrow, t);
            __syncthreads();
        }
    }

    // epilogue: relu + bias, split to bf16 hi/lo, cols < 100
    const int g  = lane >> 2;
    const int t4 = lane & 3;
#pragma unroll
    for (int mf = 0; mf < 4; mf++)
#pragma unroll
        for (int nf = 0; nf < 4; nf++) {
            int col = wn * 32 + nf * 8 + t4 * 2;
            if (col < NOUT) {
                float b0 = __ldg(lin_b + col), b1 = __ldg(lin_b + col + 1);
                int r1 = row0 + wm * 64 + mf * 16 + g;
                float v0 = fmaxf(acc[mf][nf][0] + b0, 0.0f);
                float v1 = fmaxf(acc[mf][nf][1] + b1, 0.0f);
                float v2 = fmaxf(acc[mf][nf][2] + b0, 0.0f);
                float v3 = fmaxf(acc[mf][nf][3] + b1, 0.0f);
                __nv_bfloat162 h0, l0, h1, l1;
                h0.x = __float2bfloat16_rn(v0);
                h0.y = __float2bfloat16_rn(v1);
                l0.x = __float2bfloat16_rn(v0 - __bfloat162float(h0.x));
                l0.y = __float2bfloat16_rn(v1 - __bfloat162float(h0.y));
                h1.x = __float2bfloat16_rn(v2);
                h1.y = __float2bfloat16_rn(v3);
                l1.x = __float2bfloat16_rn(v2 - __bfloat162float(h1.x));
                l1.y = __float2bfloat16_rn(v3 - __bfloat162float(h1.y));
                *(__nv_bfloat162*)(g_Xhi + (size_t)r1 * K2PAD + col) = h0;
                *(__nv_bfloat162*)(g_Xlo + (size_t)r1 * K2PAD + col) = l0;
                *(__nv_bfloat162*)(g_Xhi + (size_t)(r1 + 8) * K2PAD + col) = h1;
                *(__nv_bfloat162*)(g_Xlo + (size_t)(r1 + 8) * K2PAD + col) = l1;
            }
        }
}

// ---------------- K2: XG = Xlin @ b_wih^T + (bih+bhh) via bf16 mma ---------
// Tile 128x64, K=112 (7 chunks). 8 warps: wm=w&3 (32 rows, mf=2),
// wn=w>>2 (32 cols, nf=4). Fragments loaded directly from global (4B each).
__global__ __launch_bounds__(256)
void gemm2_kernel() {
    const int tid  = threadIdx.x;
    const int lane = tid & 31;
    const int w    = tid >> 5;
    const int wm   = w & 3;
    const int wn   = w >> 2;
    const int g    = lane >> 2;
    const int t4   = lane & 3;
    const int row0 = blockIdx.x * 128 + wm * 32;

    float acc[2][4][4];
#pragma unroll
    for (int a = 0; a < 2; a++)
#pragma unroll
        for (int b = 0; b < 4; b++)
#pragma unroll
            for (int c = 0; c < 4; c++) acc[a][b][c] = 0.0f;

#pragma unroll
    for (int kc = 0; kc < 7; kc++) {
        const int k0 = kc * 16 + t4 * 2;
        u32 ah[2][4], al[2][4], bh[4][2], bl[4][2];
#pragma unroll
        for (int mf = 0; mf < 2; mf++) {
            size_t base = (size_t)(row0 + mf * 16 + g) * K2PAD + k0;
            ah[mf][0] = *(const u32*)(g_Xhi + base);
            ah[mf][1] = *(const u32*)(g_Xhi + base + 8 * K2PAD);
            ah[mf][2] = *(const u32*)(g_Xhi + base + 8);
            ah[mf][3] = *(const u32*)(g_Xhi + base + 8 * K2PAD + 8);
            al[mf][0] = *(const u32*)(g_Xlo + base);
            al[mf][1] = *(const u32*)(g_Xlo + base + 8 * K2PAD);
            al[mf][2] = *(const u32*)(g_Xlo + base + 8);
            al[mf][3] = *(const u32*)(g_Xlo + base + 8 * K2PAD + 8);
        }
#pragma unroll
        for (int nf = 0; nf < 4; nf++) {
            int nbase = (wn * 32 + nf * 8 + g) * K2PAD + k0;
            bh[nf][0] = *(const u32*)(g_Wbhi + nbase);
            bh[nf][1] = *(const u32*)(g_Wbhi + nbase + 8);
            bl[nf][0] = *(const u32*)(g_Wblo + nbase);
            bl[nf][1] = *(const u32*)(g_Wblo + nbase + 8);
        }
#pragma unroll
        for (int mf = 0; mf < 2; mf++)
#pragma unroll
            for (int nf = 0; nf < 4; nf++) {
                mma_bf16(acc[mf][nf], ah[mf], bh[nf]);
                mma_bf16(acc[mf][nf], ah[mf], bl[nf]);
                mma_bf16(acc[mf][nf], al[mf], bh[nf]);
            }
    }

#pragma unroll
    for (int mf = 0; mf < 2; mf++)
#pragma unroll
        for (int nf = 0; nf < 4; nf++) {
            int col = wn * 32 + nf * 8 + t4 * 2;
            float b0 = g_gb[col], b1 = g_gb[col + 1];
            int r = row0 + mf * 16 + g;
            float2 v0, v1;
            v0.x = acc[mf][nf][0] + b0;
            v0.y = acc[mf][nf][1] + b1;
            v1.x = acc[mf][nf][2] + b0;
            v1.y = acc[mf][nf][3] + b1;
            *(float2*)(g_XG + (size_t)r * 64 + col) = v0;
            *(float2*)(g_XG + (size_t)(r + 8) * 64 + col) = v1;
        }
}

// ---------------- K3: beats LSTM, one warp per sequence --------------------
// H=16, T=8. lanes 0..15: i,g rows; lanes 16..31: f,o rows.
// xg fully prefetched; approx activations.
__global__ __launch_bounds__(256)
void beats_kernel(const float* __restrict__ whh, float* __restrict__ out) {
    const int warp = (blockIdx.x * blockDim.x + threadIdx.x) >> 5;
    const int lane = threadIdx.x & 31;
    if (warp >= NSEQ_B) return;

    float w0[16], w1[16];
#pragma unroll
    for (int j = 0; j < 16; j++) {
        w0[j] = whh[lane * 16 + j];
        w1[j] = whh[(lane + 32) * 16 + j];
    }

    const float* xg = g_XG + (size_t)warp * 512;
    float pa[8], pb[8];
#pragma unroll
    for (int t = 0; t < 8; t++) {
        pa[t] = xg[t * 64 + lane];
        pb[t] = xg[t * 64 + lane + 32];
    }

    float h = 0.0f, c = 0.0f;
    float* ob = out + (size_t)warp * 128;
    const bool lo = lane < 16;

#pragma unroll
    for (int t = 0; t < 8; t++) {
        float ga = pa[t];
        float gb = pb[t];
#pragma unroll
        for (int j = 0; j < 16; j++) {
            float hj = __shfl_sync(0xffffffffu, h, j);
            ga = fmaf(w0[j], hj, ga);
            gb = fmaf(w1[j], hj, gb);
        }
        float A, Bv;
        if (lo) {
            A  = sig_(ga) * tanha_(gb);   // sig(i)*tanh(g)
            Bv = 0.0f;
        } else {
            A  = sig_(ga);                // sig(f)
            Bv = sig_(gb);                // sig(o)
        }
        float fj = __shfl_sync(0xffffffffu, A,  lane + 16);
        float oj = __shfl_sync(0xffffffffu, Bv, lane + 16);
        if (lo) {
            c = fmaf(fj, c, A);
            h = oj * tanha_(c);
            ob[t * 16 + lane] = h;
        }
    }
}

// ---------------- K4: bars bidirectional LSTM ------------------------------
__global__ void bars_kernel(const float* __restrict__ f_wih,
                            const float* __restrict__ f_whh,
                            const float* __restrict__ f_bih,
                            const float* __restrict__ f_bhh,
                            const float* __restrict__ r_wih,
                            const float* __restrict__ r_whh,
                            const float* __restrict__ r_bih,
                            const float* __restrict__ r_bhh,
                            float* __restrict__ out) {
    __shared__ float s_wih[16][128];
    __shared__ float s_whh[32][128];
    __shared__ float s_b[128];

    const int d = blockIdx.y;
    const float* wih  = d ? r_wih : f_wih;
    const float* whh  = d ? r_whh : f_whh;
    const float* bihp = d ? r_bih : f_bih;
    const float* bhhp = d ? r_bhh : f_bhh;

    for (int i = threadIdx.x; i < 128 * 16; i += blockDim.x) {
        int g = i >> 4, j = i & 15;
        s_wih[j][g] = wih[i];
    }
    for (int i = threadIdx.x; i < 128 * 32; i += blockDim.x) {
        int g = i >> 5, j = i & 31;
        s_whh[j][g] = whh[i];
    }
    if (threadIdx.x < 128) s_b[threadIdx.x] = bihp[threadIdx.x] + bhhp[threadIdx.x];
    __syncthreads();

    const int warp = threadIdx.x >> 5;
    const int lane = threadIdx.x & 31;
    const int n = blockIdx.x * 8 + warp;

    const float* beats = out;
    float* bars = out + BARS_OUT_OFF;

    float h = 0.0f, c = 0.0f;
    for (int s = 0; s < 4; s++) {
        int t = d ? (3 - s) : s;
        float xv = 0.0f;
        if (lane < 16)
            xv = beats[(((size_t)n * 4 + t) * 8 + 7) * 16 + lane];

        float gi = s_b[lane];
        float gf = s_b[32 + lane];
        float gg = s_b[64 + lane];
        float go = s_b[96 + lane];
#pragma unroll
        for (int j = 0; j < 16; j++) {
            float xj = __shfl_sync(0xffffffffu, xv, j);
            gi = fmaf(s_wih[j][lane],      xj, gi);
            gf = fmaf(s_wih[j][32 + lane], xj, gf);
            gg = fmaf(s_wih[j][64 + lane], xj, gg);
            go = fmaf(s_wih[j][96 + lane], xj, go);
        }
#pragma unroll
        for (int j = 0; j < 32; j++) {
            float hj = __shfl_sync(0xffffffffu, h, j);
            gi = fmaf(s_whh[j][lane],      hj, gi);
            gf = fmaf(s_whh[j][32 + lane], hj, gf);
            gg = fmaf(s_whh[j][64 + lane], hj, gg);
            go = fmaf(s_whh[j][96 + lane], hj, go);
        }
        c = fmaf(sig_(gf), c, sig_(gi) * tanha_(gg));
        h = sig_(go) * tanha_(c);
        bars[((size_t)n * 4 + t) * 64 + d * 32 + lane] = h;
    }
}

// ---------------- launch ----------------------------------------------------
extern "C" void kernel_launch(void* const* d_in, const int* in_sizes, int n_in,
                              void* d_out, int out_size) {
    const float* channels = (const float*)d_in[0];
    const float* lin_w    = (const float*)d_in[1];
    const float* lin_b    = (const float*)d_in[2];
    const float* b_wih    = (const float*)d_in[3];
    const float* b_whh    = (const float*)d_in[4];
    const float* b_bih    = (const float*)d_in[5];
    const float* b_bhh    = (const float*)d_in[6];
    const float* f_wih    = (const float*)d_in[7];
    const float* f_whh    = (const float*)d_in[8];
    const float* f_bih    = (const float*)d_in[9];
    const float* f_bhh    = (const float*)d_in[10];
    const float* r_wih    = (const float*)d_in[11];
    const float* r_whh    = (const float*)d_in[12];
    const float* r_bih    = (const float*)d_in[13];
    const float* r_bhh    = (const float*)d_in[14];
    float* out = (float*)d_out;

    cudaFuncSetAttribute(gemm1_kernel,
                         cudaFuncAttributeMaxDynamicSharedMemorySize, SMEM_TOTAL);

    int prep_n = 128 * KPAD + 64 * K2PAD + 64;
    prep_kernel<<<(prep_n + 255) / 256, 256>>>(lin_w, b_wih, b_bih, b_bhh);
    gemm1_kernel<<<NROWS / 128, 256, SMEM_TOTAL>>>(channels, lin_b);
    gemm2_kernel<<<NROWS / 128, 256>>>();
    beats_kernel<<<NSEQ_B * 32 / 256, 256>>>(b_whh, out);
    dim3 g4(NSEQ_R / 8, 2);
    bars_kernel<<<g4, 256>>>(f_wih, f_whh, f_bih, f_bhh,
                             r_wih, r_whh, r_bih, r_bhh, out);
}

// round 8
// speedup vs baseline: 4.4302x; 1.4790x over previous
#include <cuda_runtime.h>
#include <cuda_bf16.h>
#include <cuda_fp16.h>
#include <cstdint>

// ---------------- problem constants ----------------
#define NROWS   32768        // B*BARS*BEATS*FRAC
#define KF      940          // input features (10*2*47)
#define KPAD    960          // K padded to 30 x 32
#define NOUT    100          // linear out
#define K2PAD   112          // padded K for gemm2 (7 x 16)
#define NSEQ_B  4096         // beats LSTM sequences
#define NSEQ_R  1024         // bars LSTM sequences
#define BEATS_OUT_ELEMS (32768 * 16)
#define BARS_OUT_OFF    BEATS_OUT_ELEMS
#define SSTR    40           // smem row stride in b16 elems (80B, 16B-aligned)
#define ARR_ELEMS (128 * SSTR)   // 5120 elems per array

typedef unsigned int u32;

// ---------------- scratch ----------------
__device__ __half g_Whf[128 * KPAD];           // linear weight fp16 (permuted)
__device__ __nv_bfloat16 g_Wbhi[64 * K2PAD];   // beats wih split (bf16 hi/lo)
__device__ __nv_bfloat16 g_Wblo[64 * K2PAD];
__device__ float g_gb[64];
// Xlin as bf16 hi/lo, row stride K2PAD; pad cols [100,112) never written -> stay 0
__device__ __nv_bfloat16 g_Xhi[(size_t)NROWS * K2PAD];
__device__ __nv_bfloat16 g_Xlo[(size_t)NROWS * K2PAD];
__device__ float g_XG[(size_t)NROWS * 64];

// ---------------- fast activations ----------------
__device__ __forceinline__ float tanha_(float x) {
    float y;
    asm("tanh.approx.f32 %0, %1;" : "=f"(y) : "f"(x));
    return y;
}
__device__ __forceinline__ float sig_(float x) {
    return fmaf(tanha_(0.5f * x), 0.5f, 0.5f);
}

// ---------------- K0: permute weights (fp16), split beats weights ----------
__global__ void prep_kernel(const float* __restrict__ lin_w,
                            const float* __restrict__ b_wih,
                            const float* __restrict__ b_bih,
                            const float* __restrict__ b_bhh) {
    int idx = blockIdx.x * blockDim.x + threadIdx.x;
    if (idx < 128 * KPAD) {
        int o = idx / KPAD;
        int m = idx % KPAD;
        float v = 0.0f;
        if (o < NOUT && m < KF) {
            int c10 = m / 94;
            int r   = m % 94;
            int c2  = r / 47;
            int c47 = r % 47;
            v = lin_w[o * KF + c10 * 94 + c47 * 2 + c2];
        }
        g_Whf[idx] = __float2half_rn(v);
    } else if (idx < 128 * KPAD + 64 * K2PAD) {
        int j = idx - 128 * KPAD;
        int n = j / K2PAD;
        int k = j % K2PAD;
        float v = (k < NOUT) ? b_wih[n * NOUT + k] : 0.0f;
        __nv_bfloat16 hi = __float2bfloat16_rn(v);
        g_Wbhi[j] = hi;
        g_Wblo[j] = __float2bfloat16_rn(v - __bfloat162float(hi));
    } else if (idx < 128 * KPAD + 64 * K2PAD + 64) {
        int j = idx - 128 * KPAD - 64 * K2PAD;
        g_gb[j] = b_bih[j] + b_bhh[j];
    }
}

// ---------------- mma helpers ----------------
__device__ __forceinline__ void ldsm4(u32& r0, u32& r1, u32& r2, u32& r3,
                                      u32 addr) {
    asm volatile("ldmatrix.sync.aligned.m8n8.x4.shared.b16 {%0,%1,%2,%3},[%4];"
                 : "=r"(r0), "=r"(r1), "=r"(r2), "=r"(r3) : "r"(addr));
}
__device__ __forceinline__ void ldsm2(u32& r0, u32& r1, u32 addr) {
    asm volatile("ldmatrix.sync.aligned.m8n8.x2.shared.b16 {%0,%1},[%2];"
                 : "=r"(r0), "=r"(r1) : "r"(addr));
}
__device__ __forceinline__ void mma_f16(float* c, const u32* a, const u32* b) {
    asm volatile(
        "mma.sync.aligned.m16n8k16.row.col.f32.f16.f16.f32 "
        "{%0,%1,%2,%3},{%4,%5,%6,%7},{%8,%9},{%0,%1,%2,%3};"
        : "+f"(c[0]), "+f"(c[1]), "+f"(c[2]), "+f"(c[3])
        : "r"(a[0]), "r"(a[1]), "r"(a[2]), "r"(a[3]), "r"(b[0]), "r"(b[1]));
}
__device__ __forceinline__ void mma_bf16(float* c, const u32* a, const u32* b) {
    asm volatile(
        "mma.sync.aligned.m16n8k16.row.col.f32.bf16.bf16.f32 "
        "{%0,%1,%2,%3},{%4,%5,%6,%7},{%8,%9},{%0,%1,%2,%3};"
        : "+f"(c[0]), "+f"(c[1]), "+f"(c[2]), "+f"(c[3])
        : "r"(a[0]), "r"(a[1]), "r"(a[2]), "r"(a[3]), "r"(b[0]), "r"(b[1]));
}

// Register staging for the double-buffer prefetch in gemm1.
struct TileRegs {
    float x[16];
    uint4 wh[2];
};

__device__ __forceinline__ void load_tile(int K0, int lc,
                                          const float* __restrict__ xrow,
                                          const __half* __restrict__ wrow,
                                          TileRegs& t) {
#pragma unroll
    for (int j = 0; j < 4; j++) {
        int kb = K0 + lc + j * 4;
        if (kb + 3 < KF) {
            float4 v = *(const float4*)(xrow + K0 + j * 4);
            t.x[j * 4 + 0] = v.x; t.x[j * 4 + 1] = v.y;
            t.x[j * 4 + 2] = v.z; t.x[j * 4 + 3] = v.w;
        } else {
#pragma unroll
            for (int e = 0; e < 4; e++)
                t.x[j * 4 + e] = (kb + e < KF) ? xrow[K0 + j * 4 + e] : 0.0f;
        }
    }
    t.wh[0] = *(const uint4*)(wrow + K0);
    t.wh[1] = *(const uint4*)(wrow + K0 + 8);
}

__device__ __forceinline__ void store_tile(__half* bufbase, int off,
                                           const TileRegs& t) {
    __half* xp = bufbase + off;
    __half* wp = bufbase + ARR_ELEMS + off;
#pragma unroll
    for (int p = 0; p < 8; p++) {
        __half2 h = __floats2half2_rn(t.x[2 * p], t.x[2 * p + 1]);
        *(__half2*)(xp + 2 * p) = h;
    }
    *(uint4*)wp       = t.wh[0];
    *(uint4*)(wp + 8) = t.wh[1];
}

// ---------------- K1: Xlin = relu(X @ W^T + b), single-pass fp16 mma -------
// BM=128, BN=128, BK=32, 256 threads, warp tile 64x32, double-buffered smem.
__global__ __launch_bounds__(256, 2)
void gemm1_kernel(const float* __restrict__ X, const float* __restrict__ lin_b) {
    __shared__ __align__(16) __half smem[2 * 2 * ARR_ELEMS];   // 40 KB

    const int tid  = threadIdx.x;
    const int row0 = blockIdx.x * 128;
    const int lr   = tid >> 1;        // 0..127 loader row
    const int lc   = (tid & 1) * 16;  // 0 / 16 loader col base
    const int soff = lr * SSTR + lc;

    const float* xrow = X + (size_t)(row0 + lr) * KF + lc;
    const __half* wrow = g_Whf + lr * KPAD + lc;

    // ldmatrix lane geometry
    const int lane = tid & 31;
    const int w    = tid >> 5;
    const int wm   = w & 1;       // 0..1  -> 64-row half
    const int wn   = w >> 1;      // 0..3  -> 32-col quarter
    const int dra  = ((lane >> 3) & 1) * 8 + (lane & 7);
    const int dca  = (lane >> 4) * 8;
    const int aoff = (wm * 64 + dra) * SSTR + dca;   // + mf*16*SSTR + kf
    const int l2   = lane & 15;
    const int boff = (wn * 32 + (l2 & 7)) * SSTR + (l2 >> 3) * 8;  // + nf*8*SSTR + kf

    const u32 sbase = (u32)__cvta_generic_to_shared(smem);

    float acc[4][4][4];
#pragma unroll
    for (int a = 0; a < 4; a++)
#pragma unroll
        for (int b = 0; b < 4; b++)
#pragma unroll
            for (int c = 0; c < 4; c++) acc[a][b][c] = 0.0f;

    TileRegs t;
    load_tile(0, lc, xrow, wrow, t);
    store_tile(smem, soff, t);                // buffer 0
    load_tile(32, lc, xrow, wrow, t);         // tile 1 staged in regs
    __syncthreads();

    for (int it = 0; it < 30; ++it) {
        const u32 cb = sbase + (u32)((it & 1) * (2 * ARR_ELEMS * 2));

#pragma unroll
        for (int kf = 0; kf < 32; kf += 16) {
            u32 af[4][4];
            u32 bf[4][2];
#pragma unroll
            for (int mf = 0; mf < 4; mf++) {
                u32 ea = (u32)(aoff + mf * 16 * SSTR + kf) * 2u;
                ldsm4(af[mf][0], af[mf][1], af[mf][2], af[mf][3], cb + ea);
            }
#pragma unroll
            for (int nf = 0; nf < 4; nf++) {
                u32 eb = (u32)(boff + nf * 8 * SSTR + kf) * 2u
                         + (u32)(ARR_ELEMS * 2);
                ldsm2(bf[nf][0], bf[nf][1], cb + eb);
            }
#pragma unroll
            for (int mf = 0; mf < 4; mf++)
#pragma unroll
                for (int nf = 0; nf < 4; nf++)
                    mma_f16(acc[mf][nf], af[mf], bf[nf]);
        }

        if (it + 1 < 30) {
            store_tile(smem + ((it + 1) & 1) * (2 * ARR_ELEMS), soff, t);
            if (it + 2 < 30) load_tile((it + 2) * 32, lc, xrow, wrow, t);
            __syncthreads();
        }
    }

    // epilogue: relu + bias, split to bf16 hi/lo, cols < 100
    const int g  = lane >> 2;
    const int t4 = lane & 3;
#pragma unroll
    for (int mf = 0; mf < 4; mf++)
#pragma unroll
        for (int nf = 0; nf < 4; nf++) {
            int col = wn * 32 + nf * 8 + t4 * 2;
            if (col < NOUT) {
                float b0 = __ldg(lin_b + col), b1 = __ldg(lin_b + col + 1);
                int r1 = row0 + wm * 64 + mf * 16 + g;
                float v0 = fmaxf(acc[mf][nf][0] + b0, 0.0f);
                float v1 = fmaxf(acc[mf][nf][1] + b1, 0.0f);
                float v2 = fmaxf(acc[mf][nf][2] + b0, 0.0f);
                float v3 = fmaxf(acc[mf][nf][3] + b1, 0.0f);
                __nv_bfloat162 h0, l0, h1, l1;
                h0.x = __float2bfloat16_rn(v0);
                h0.y = __float2bfloat16_rn(v1);
                l0.x = __float2bfloat16_rn(v0 - __bfloat162float(h0.x));
                l0.y = __float2bfloat16_rn(v1 - __bfloat162float(h0.y));
                h1.x = __float2bfloat16_rn(v2);
                h1.y = __float2bfloat16_rn(v3);
                l1.x = __float2bfloat16_rn(v2 - __bfloat162float(h1.x));
                l1.y = __float2bfloat16_rn(v3 - __bfloat162float(h1.y));
                *(__nv_bfloat162*)(g_Xhi + (size_t)r1 * K2PAD + col) = h0;
                *(__nv_bfloat162*)(g_Xlo + (size_t)r1 * K2PAD + col) = l0;
                *(__nv_bfloat162*)(g_Xhi + (size_t)(r1 + 8) * K2PAD + col) = h1;
                *(__nv_bfloat162*)(g_Xlo + (size_t)(r1 + 8) * K2PAD + col) = l1;
            }
        }
}

// ---------------- K2: XG = Xlin @ b_wih^T + (bih+bhh) via bf16 mma ---------
__global__ __launch_bounds__(256)
void gemm2_kernel() {
    const int tid  = threadIdx.x;
    const int lane = tid & 31;
    const int w    = tid >> 5;
    const int wm   = w & 3;
    const int wn   = w >> 2;
    const int g    = lane >> 2;
    const int t4   = lane & 3;
    const int row0 = blockIdx.x * 128 + wm * 32;

    float acc[2][4][4];
#pragma unroll
    for (int a = 0; a < 2; a++)
#pragma unroll
        for (int b = 0; b < 4; b++)
#pragma unroll
            for (int c = 0; c < 4; c++) acc[a][b][c] = 0.0f;

#pragma unroll
    for (int kc = 0; kc < 7; kc++) {
        const int k0 = kc * 16 + t4 * 2;
        u32 ah[2][4], al[2][4], bh[4][2], bl[4][2];
#pragma unroll
        for (int mf = 0; mf < 2; mf++) {
            size_t base = (size_t)(row0 + mf * 16 + g) * K2PAD + k0;
            ah[mf][0] = *(const u32*)(g_Xhi + base);
            ah[mf][1] = *(const u32*)(g_Xhi + base + 8 * K2PAD);
            ah[mf][2] = *(const u32*)(g_Xhi + base + 8);
            ah[mf][3] = *(const u32*)(g_Xhi + base + 8 * K2PAD + 8);
            al[mf][0] = *(const u32*)(g_Xlo + base);
            al[mf][1] = *(const u32*)(g_Xlo + base + 8 * K2PAD);
            al[mf][2] = *(const u32*)(g_Xlo + base + 8);
            al[mf][3] = *(const u32*)(g_Xlo + base + 8 * K2PAD + 8);
        }
#pragma unroll
        for (int nf = 0; nf < 4; nf++) {
            int nbase = (wn * 32 + nf * 8 + g) * K2PAD + k0;
            bh[nf][0] = *(const u32*)(g_Wbhi + nbase);
            bh[nf][1] = *(const u32*)(g_Wbhi + nbase + 8);
            bl[nf][0] = *(const u32*)(g_Wblo + nbase);
            bl[nf][1] = *(const u32*)(g_Wblo + nbase + 8);
        }
#pragma unroll
        for (int mf = 0; mf < 2; mf++)
#pragma unroll
            for (int nf = 0; nf < 4; nf++) {
                mma_bf16(acc[mf][nf], ah[mf], bh[nf]);
                mma_bf16(acc[mf][nf], ah[mf], bl[nf]);
                mma_bf16(acc[mf][nf], al[mf], bh[nf]);
            }
    }

#pragma unroll
    for (int mf = 0; mf < 2; mf++)
#pragma unroll
        for (int nf = 0; nf < 4; nf++) {
            int col = wn * 32 + nf * 8 + t4 * 2;
            float b0 = g_gb[col], b1 = g_gb[col + 1];
            int r = row0 + mf * 16 + g;
            float2 v0, v1;
            v0.x = acc[mf][nf][0] + b0;
            v0.y = acc[mf][nf][1] + b1;
            v1.x = acc[mf][nf][2] + b0;
            v1.y = acc[mf][nf][3] + b1;
            *(float2*)(g_XG + (size_t)r * 64 + col) = v0;
            *(float2*)(g_XG + (size_t)(r + 8) * 64 + col) = v1;
        }
}

// ---------------- K3: beats LSTM, one warp per sequence --------------------
__global__ __launch_bounds__(256)
void beats_kernel(const float* __restrict__ whh, float* __restrict__ out) {
    const int warp = (blockIdx.x * blockDim.x + threadIdx.x) >> 5;
    const int lane = threadIdx.x & 31;
    if (warp >= NSEQ_B) return;

    float w0[16], w1[16];
#pragma unroll
    for (int j = 0; j < 16; j++) {
        w0[j] = whh[lane * 16 + j];
        w1[j] = whh[(lane + 32) * 16 + j];
    }

    const float* xg = g_XG + (size_t)warp * 512;
    float pa[8], pb[8];
#pragma unroll
    for (int t = 0; t < 8; t++) {
        pa[t] = xg[t * 64 + lane];
        pb[t] = xg[t * 64 + lane + 32];
    }

    float h = 0.0f, c = 0.0f;
    float* ob = out + (size_t)warp * 128;
    const bool lo = lane < 16;

#pragma unroll
    for (int t = 0; t < 8; t++) {
        float ga = pa[t], gb = pb[t];
        float ga1 = 0.0f, gb1 = 0.0f;
#pragma unroll
        for (int j = 0; j < 8; j++) {
            float hj = __shfl_sync(0xffffffffu, h, j);
            ga = fmaf(w0[j], hj, ga);
            gb = fmaf(w1[j], hj, gb);
        }
#pragma unroll
        for (int j = 8; j < 16; j++) {
            float hj = __shfl_sync(0xffffffffu, h, j);
            ga1 = fmaf(w0[j], hj, ga1);
            gb1 = fmaf(w1[j], hj, gb1);
        }
        ga += ga1;
        gb += gb1;
        float A, Bv;
        if (lo) {
            A  = sig_(ga) * tanha_(gb);   // sig(i)*tanh(g)
            Bv = 0.0f;
        } else {
            A  = sig_(ga);                // sig(f)
            Bv = sig_(gb);                // sig(o)
        }
        float fj = __shfl_sync(0xffffffffu, A,  lane + 16);
        float oj = __shfl_sync(0xffffffffu, Bv, lane + 16);
        if (lo) {
            c = fmaf(fj, c, A);
            h = oj * tanha_(c);
            ob[t * 16 + lane] = h;
        }
    }
}

// ---------------- K4: bars bidirectional LSTM ------------------------------
__global__ void bars_kernel(const float* __restrict__ f_wih,
                            const float* __restrict__ f_whh,
                            const float* __restrict__ f_bih,
                            const float* __restrict__ f_bhh,
                            const float* __restrict__ r_wih,
                            const float* __restrict__ r_whh,
                            const float* __restrict__ r_bih,
                            const float* __restrict__ r_bhh,
                            float* __restrict__ out) {
    __shared__ float s_wih[16][128];
    __shared__ float s_whh[32][128];
    __shared__ float s_b[128];

    const int d = blockIdx.y;
    const float* wih  = d ? r_wih : f_wih;
    const float* whh  = d ? r_whh : f_whh;
    const float* bihp = d ? r_bih : f_bih;
    const float* bhhp = d ? r_bhh : f_bhh;

    for (int i = threadIdx.x; i < 128 * 16; i += blockDim.x) {
        int g = i >> 4, j = i & 15;
        s_wih[j][g] = wih[i];
    }
    for (int i = threadIdx.x; i < 128 * 32; i += blockDim.x) {
        int g = i >> 5, j = i & 31;
        s_whh[j][g] = whh[i];
    }
    if (threadIdx.x < 128) s_b[threadIdx.x] = bihp[threadIdx.x] + bhhp[threadIdx.x];
    __syncthreads();

    const int warp = threadIdx.x >> 5;
    const int lane = threadIdx.x & 31;
    const int n = blockIdx.x * 8 + warp;

    const float* beats = out;
    float* bars = out + BARS_OUT_OFF;

    float h = 0.0f, c = 0.0f;
    for (int s = 0; s < 4; s++) {
        int t = d ? (3 - s) : s;
        float xv = 0.0f;
        if (lane < 16)
            xv = beats[(((size_t)n * 4 + t) * 8 + 7) * 16 + lane];

        float gi = s_b[lane];
        float gf = s_b[32 + lane];
        float gg = s_b[64 + lane];
        float go = s_b[96 + lane];
#pragma unroll
        for (int j = 0; j < 16; j++) {
            float xj = __shfl_sync(0xffffffffu, xv, j);
            gi = fmaf(s_wih[j][lane],      xj, gi);
            gf = fmaf(s_wih[j][32 + lane], xj, gf);
            gg = fmaf(s_wih[j][64 + lane], xj, gg);
            go = fmaf(s_wih[j][96 + lane], xj, go);
        }
#pragma unroll
        for (int j = 0; j < 32; j++) {
            float hj = __shfl_sync(0xffffffffu, h, j);
            gi = fmaf(s_whh[j][lane],      hj, gi);
            gf = fmaf(s_whh[j][32 + lane], hj, gf);
            gg = fmaf(s_whh[j][64 + lane], hj, gg);
            go = fmaf(s_whh[j][96 + lane], hj, go);
        }
        c = fmaf(sig_(gf), c, sig_(gi) * tanha_(gg));
        h = sig_(go) * tanha_(c);
        bars[((size_t)n * 4 + t) * 64 + d * 32 + lane] = h;
    }
}

// ---------------- launch ----------------------------------------------------
extern "C" void kernel_launch(void* const* d_in, const int* in_sizes, int n_in,
                              void* d_out, int out_size) {
    const float* channels = (const float*)d_in[0];
    const float* lin_w    = (const float*)d_in[1];
    const float* lin_b    = (const float*)d_in[2];
    const float* b_wih    = (const float*)d_in[3];
    const float* b_whh    = (const float*)d_in[4];
    const float* b_bih    = (const float*)d_in[5];
    const float* b_bhh    = (const float*)d_in[6];
    const float* f_wih    = (const float*)d_in[7];
    const float* f_whh    = (const float*)d_in[8];
    const float* f_bih    = (const float*)d_in[9];
    const float* f_bhh    = (const float*)d_in[10];
    const float* r_wih    = (const float*)d_in[11];
    const float* r_whh    = (const float*)d_in[12];
    const float* r_bih    = (const float*)d_in[13];
    const float* r_bhh    = (const float*)d_in[14];
    float* out = (float*)d_out;

    int prep_n = 128 * KPAD + 64 * K2PAD + 64;
    prep_kernel<<<(prep_n + 255) / 256, 256>>>(lin_w, b_wih, b_bih, b_bhh);
    gemm1_kernel<<<NROWS / 128, 256>>>(channels, lin_b);
    gemm2_kernel<<<NROWS / 128, 256>>>();
    beats_kernel<<<NSEQ_B * 32 / 256, 256>>>(b_whh, out);
    dim3 g4(NSEQ_R / 8, 2);
    bars_kernel<<<g4, 256>>>(f_wih, f_whh, f_bih, f_bhh,
                             r_wih, r_whh, r_bih, r_bhh, out);
}

// round 9
// speedup vs baseline: 5.2706x; 1.1897x over previous
#include <cuda_runtime.h>
#include <cuda_bf16.h>
#include <cuda_fp16.h>
#include <cstdint>

// ---------------- problem constants ----------------
#define NROWS   32768        // B*BARS*BEATS*FRAC
#define KF      940          // input features (10*2*47)
#define KPAD    960          // K padded to 30 x 32
#define NOUT    100          // linear out
#define K2PAD   112          // padded K for gemm2 (7 x 16)
#define NSEQ_B  4096         // beats LSTM sequences
#define NSEQ_R  1024         // bars LSTM sequences
#define BEATS_OUT_ELEMS (32768 * 16)
#define BARS_OUT_OFF    BEATS_OUT_ELEMS
#define SSTR    40           // smem row stride in b16 elems (80B, 16B-aligned)
#define ARR_ELEMS (128 * SSTR)   // 5120 elems per array
#define XGS     66           // fused-kernel smem row stride (floats, even)

typedef unsigned int u32;

// ---------------- scratch ----------------
__device__ __half g_Whf[128 * KPAD];     // linear weight fp16 (permuted)
__device__ __half g_Wbh[64 * K2PAD];     // beats wih fp16 (padded)
__device__ float g_gb[64];
// Xlin as fp16, row stride K2PAD; pad cols [100,112) never written -> stay 0
__device__ __half g_Xh[(size_t)NROWS * K2PAD];

// ---------------- fast activations ----------------
__device__ __forceinline__ float tanha_(float x) {
    float y;
    asm("tanh.approx.f32 %0, %1;" : "=f"(y) : "f"(x));
    return y;
}
__device__ __forceinline__ float sig_(float x) {
    return fmaf(tanha_(0.5f * x), 0.5f, 0.5f);
}

// ---------------- K0: permute weights (fp16), beats weights ---------------
__global__ void prep_kernel(const float* __restrict__ lin_w,
                            const float* __restrict__ b_wih,
                            const float* __restrict__ b_bih,
                            const float* __restrict__ b_bhh) {
    int idx = blockIdx.x * blockDim.x + threadIdx.x;
    if (idx < 128 * KPAD) {
        int o = idx / KPAD;
        int m = idx % KPAD;
        float v = 0.0f;
        if (o < NOUT && m < KF) {
            int c10 = m / 94;
            int r   = m % 94;
            int c2  = r / 47;
            int c47 = r % 47;
            v = lin_w[o * KF + c10 * 94 + c47 * 2 + c2];
        }
        g_Whf[idx] = __float2half_rn(v);
    } else if (idx < 128 * KPAD + 64 * K2PAD) {
        int j = idx - 128 * KPAD;
        int n = j / K2PAD;
        int k = j % K2PAD;
        float v = (k < NOUT) ? b_wih[n * NOUT + k] : 0.0f;
        g_Wbh[j] = __float2half_rn(v);
    } else if (idx < 128 * KPAD + 64 * K2PAD + 64) {
        int j = idx - 128 * KPAD - 64 * K2PAD;
        g_gb[j] = b_bih[j] + b_bhh[j];
    }
}

// ---------------- mma helpers ----------------
__device__ __forceinline__ void ldsm4(u32& r0, u32& r1, u32& r2, u32& r3,
                                      u32 addr) {
    asm volatile("ldmatrix.sync.aligned.m8n8.x4.shared.b16 {%0,%1,%2,%3},[%4];"
                 : "=r"(r0), "=r"(r1), "=r"(r2), "=r"(r3) : "r"(addr));
}
__device__ __forceinline__ void ldsm2(u32& r0, u32& r1, u32 addr) {
    asm volatile("ldmatrix.sync.aligned.m8n8.x2.shared.b16 {%0,%1},[%2];"
                 : "=r"(r0), "=r"(r1) : "r"(addr));
}
__device__ __forceinline__ void mma_f16(float* c, const u32* a, const u32* b) {
    asm volatile(
        "mma.sync.aligned.m16n8k16.row.col.f32.f16.f16.f32 "
        "{%0,%1,%2,%3},{%4,%5,%6,%7},{%8,%9},{%0,%1,%2,%3};"
        : "+f"(c[0]), "+f"(c[1]), "+f"(c[2]), "+f"(c[3])
        : "r"(a[0]), "r"(a[1]), "r"(a[2]), "r"(a[3]), "r"(b[0]), "r"(b[1]));
}

// Register staging for the double-buffer prefetch in gemm1.
struct TileRegs {
    float x[16];
    uint4 wh[2];
};

__device__ __forceinline__ void load_tile(int K0, int lc,
                                          const float* __restrict__ xrow,
                                          const __half* __restrict__ wrow,
                                          TileRegs& t) {
#pragma unroll
    for (int j = 0; j < 4; j++) {
        int kb = K0 + lc + j * 4;
        if (kb + 3 < KF) {
            float4 v = *(const float4*)(xrow + K0 + j * 4);
            t.x[j * 4 + 0] = v.x; t.x[j * 4 + 1] = v.y;
            t.x[j * 4 + 2] = v.z; t.x[j * 4 + 3] = v.w;
        } else {
#pragma unroll
            for (int e = 0; e < 4; e++)
                t.x[j * 4 + e] = (kb + e < KF) ? xrow[K0 + j * 4 + e] : 0.0f;
        }
    }
    t.wh[0] = *(const uint4*)(wrow + K0);
    t.wh[1] = *(const uint4*)(wrow + K0 + 8);
}

__device__ __forceinline__ void store_tile(__half* bufbase, int off,
                                           const TileRegs& t) {
    __half* xp = bufbase + off;
    __half* wp = bufbase + ARR_ELEMS + off;
#pragma unroll
    for (int p = 0; p < 8; p++) {
        __half2 h = __floats2half2_rn(t.x[2 * p], t.x[2 * p + 1]);
        *(__half2*)(xp + 2 * p) = h;
    }
    *(uint4*)wp       = t.wh[0];
    *(uint4*)(wp + 8) = t.wh[1];
}

// ---------------- K1: Xlin = relu(X @ W^T + b), single-pass fp16 mma -------
__global__ __launch_bounds__(256, 2)
void gemm1_kernel(const float* __restrict__ X, const float* __restrict__ lin_b) {
    __shared__ __align__(16) __half smem[2 * 2 * ARR_ELEMS];   // 40 KB

    const int tid  = threadIdx.x;
    const int row0 = blockIdx.x * 128;
    const int lr   = tid >> 1;        // 0..127 loader row
    const int lc   = (tid & 1) * 16;  // 0 / 16 loader col base
    const int soff = lr * SSTR + lc;

    const float* xrow = X + (size_t)(row0 + lr) * KF + lc;
    const __half* wrow = g_Whf + lr * KPAD + lc;

    // ldmatrix lane geometry
    const int lane = tid & 31;
    const int w    = tid >> 5;
    const int wm   = w & 1;
    const int wn   = w >> 1;
    const int dra  = ((lane >> 3) & 1) * 8 + (lane & 7);
    const int dca  = (lane >> 4) * 8;
    const int aoff = (wm * 64 + dra) * SSTR + dca;
    const int l2   = lane & 15;
    const int boff = (wn * 32 + (l2 & 7)) * SSTR + (l2 >> 3) * 8;

    const u32 sbase = (u32)__cvta_generic_to_shared(smem);

    float acc[4][4][4];
#pragma unroll
    for (int a = 0; a < 4; a++)
#pragma unroll
        for (int b = 0; b < 4; b++)
#pragma unroll
            for (int c = 0; c < 4; c++) acc[a][b][c] = 0.0f;

    TileRegs t;
    load_tile(0, lc, xrow, wrow, t);
    store_tile(smem, soff, t);
    load_tile(32, lc, xrow, wrow, t);
    __syncthreads();

    for (int it = 0; it < 30; ++it) {
        const u32 cb = sbase + (u32)((it & 1) * (2 * ARR_ELEMS * 2));

#pragma unroll
        for (int kf = 0; kf < 32; kf += 16) {
            u32 af[4][4];
            u32 bf[4][2];
#pragma unroll
            for (int mf = 0; mf < 4; mf++) {
                u32 ea = (u32)(aoff + mf * 16 * SSTR + kf) * 2u;
                ldsm4(af[mf][0], af[mf][1], af[mf][2], af[mf][3], cb + ea);
            }
#pragma unroll
            for (int nf = 0; nf < 4; nf++) {
                u32 eb = (u32)(boff + nf * 8 * SSTR + kf) * 2u
                         + (u32)(ARR_ELEMS * 2);
                ldsm2(bf[nf][0], bf[nf][1], cb + eb);
            }
#pragma unroll
            for (int mf = 0; mf < 4; mf++)
#pragma unroll
                for (int nf = 0; nf < 4; nf++)
                    mma_f16(acc[mf][nf], af[mf], bf[nf]);
        }

        if (it + 1 < 30) {
            store_tile(smem + ((it + 1) & 1) * (2 * ARR_ELEMS), soff, t);
            if (it + 2 < 30) load_tile((it + 2) * 32, lc, xrow, wrow, t);
            __syncthreads();
        }
    }

    // epilogue: relu + bias, fp16, cols < 100
    const int g  = lane >> 2;
    const int t4 = lane & 3;
#pragma unroll
    for (int mf = 0; mf < 4; mf++)
#pragma unroll
        for (int nf = 0; nf < 4; nf++) {
            int col = wn * 32 + nf * 8 + t4 * 2;
            if (col < NOUT) {
                float b0 = __ldg(lin_b + col), b1 = __ldg(lin_b + col + 1);
                int r1 = row0 + wm * 64 + mf * 16 + g;
                float v0 = fmaxf(acc[mf][nf][0] + b0, 0.0f);
                float v1 = fmaxf(acc[mf][nf][1] + b1, 0.0f);
                float v2 = fmaxf(acc[mf][nf][2] + b0, 0.0f);
                float v3 = fmaxf(acc[mf][nf][3] + b1, 0.0f);
                *(__half2*)(g_Xh + (size_t)r1 * K2PAD + col) =
                    __floats2half2_rn(v0, v1);
                *(__half2*)(g_Xh + (size_t)(r1 + 8) * K2PAD + col) =
                    __floats2half2_rn(v2, v3);
            }
        }
}

// ---------------- K2: fused gates GEMM + beats LSTM ------------------------
// Tile 128 rows = 16 complete sequences. mma phase computes gates into smem,
// then 8 warps run the LSTM (2 sequences each) and write beats output.
__global__ __launch_bounds__(256)
void gemm2_beats(const float* __restrict__ whh, float* __restrict__ out) {
    __shared__ float sXG[128 * XGS];   // 33.8 KB

    const int tid  = threadIdx.x;
    const int lane = tid & 31;
    const int w    = tid >> 5;
    const int wm   = w & 3;
    const int wn   = w >> 2;
    const int g    = lane >> 2;
    const int t4   = lane & 3;
    const int rloc = wm * 32;                  // local row base of this warp
    const int row0 = blockIdx.x * 128 + rloc;  // global row base

    float acc[2][4][4];
#pragma unroll
    for (int a = 0; a < 2; a++)
#pragma unroll
        for (int b = 0; b < 4; b++)
#pragma unroll
            for (int c = 0; c < 4; c++) acc[a][b][c] = 0.0f;

#pragma unroll
    for (int kc = 0; kc < 7; kc++) {
        const int k0 = kc * 16 + t4 * 2;
        u32 af[2][4], bf[4][2];
#pragma unroll
        for (int mf = 0; mf < 2; mf++) {
            size_t base = (size_t)(row0 + mf * 16 + g) * K2PAD + k0;
            af[mf][0] = *(const u32*)(g_Xh + base);
            af[mf][1] = *(const u32*)(g_Xh + base + 8 * K2PAD);
            af[mf][2] = *(const u32*)(g_Xh + base + 8);
            af[mf][3] = *(const u32*)(g_Xh + base + 8 * K2PAD + 8);
        }
#pragma unroll
        for (int nf = 0; nf < 4; nf++) {
            int nbase = (wn * 32 + nf * 8 + g) * K2PAD + k0;
            bf[nf][0] = *(const u32*)(g_Wbh + nbase);
            bf[nf][1] = *(const u32*)(g_Wbh + nbase + 8);
        }
#pragma unroll
        for (int mf = 0; mf < 2; mf++)
#pragma unroll
            for (int nf = 0; nf < 4; nf++)
                mma_f16(acc[mf][nf], af[mf], bf[nf]);
    }

    // gates + bias -> smem
#pragma unroll
    for (int mf = 0; mf < 2; mf++)
#pragma unroll
        for (int nf = 0; nf < 4; nf++) {
            int col = wn * 32 + nf * 8 + t4 * 2;
            float b0 = g_gb[col], b1 = g_gb[col + 1];
            int r = rloc + mf * 16 + g;
            *(float2*)(sXG + r * XGS + col) =
                make_float2(acc[mf][nf][0] + b0, acc[mf][nf][1] + b1);
            *(float2*)(sXG + (r + 8) * XGS + col) =
                make_float2(acc[mf][nf][2] + b0, acc[mf][nf][3] + b1);
        }
    __syncthreads();

    // ---- beats LSTM: warp w handles local seqs 2w, 2w+1 ----
    float w0[16], w1[16];
#pragma unroll
    for (int j = 0; j < 16; j++) {
        w0[j] = whh[lane * 16 + j];
        w1[j] = whh[(lane + 32) * 16 + j];
    }
    const bool lo = lane < 16;

#pragma unroll
    for (int s2 = 0; s2 < 2; s2++) {
        const int sl = w * 2 + s2;                 // local seq 0..15
        float pa[8], pb[8];
#pragma unroll
        for (int t = 0; t < 8; t++) {
            pa[t] = sXG[(sl * 8 + t) * XGS + lane];
            pb[t] = sXG[(sl * 8 + t) * XGS + lane + 32];
        }
        float h = 0.0f, c = 0.0f;
        float* ob = out + ((size_t)blockIdx.x * 16 + sl) * 128;
#pragma unroll
        for (int t = 0; t < 8; t++) {
            float ga = pa[t], gb = pb[t];
            float ga1 = 0.0f, gb1 = 0.0f;
#pragma unroll
            for (int j = 0; j < 8; j++) {
                float hj = __shfl_sync(0xffffffffu, h, j);
                ga = fmaf(w0[j], hj, ga);
                gb = fmaf(w1[j], hj, gb);
            }
#pragma unroll
            for (int j = 8; j < 16; j++) {
                float hj = __shfl_sync(0xffffffffu, h, j);
                ga1 = fmaf(w0[j], hj, ga1);
                gb1 = fmaf(w1[j], hj, gb1);
            }
            ga += ga1;
            gb += gb1;
            float A, Bv;
            if (lo) {
                A  = sig_(ga) * tanha_(gb);   // sig(i)*tanh(g)
                Bv = 0.0f;
            } else {
                A  = sig_(ga);                // sig(f)
                Bv = sig_(gb);                // sig(o)
            }
            float fj = __shfl_sync(0xffffffffu, A,  lane + 16);
            float oj = __shfl_sync(0xffffffffu, Bv, lane + 16);
            if (lo) {
                c = fmaf(fj, c, A);
                h = oj * tanha_(c);
                ob[t * 16 + lane] = h;
            }
        }
    }
}

// ---------------- K3: bars bidirectional LSTM ------------------------------
__global__ void bars_kernel(const float* __restrict__ f_wih,
                            const float* __restrict__ f_whh,
                            const float* __restrict__ f_bih,
                            const float* __restrict__ f_bhh,
                            const float* __restrict__ r_wih,
                            const float* __restrict__ r_whh,
                            const float* __restrict__ r_bih,
                            const float* __restrict__ r_bhh,
                            float* __restrict__ out) {
    __shared__ float s_wih[16][128];
    __shared__ float s_whh[32][128];
    __shared__ float s_b[128];

    const int d = blockIdx.y;
    const float* wih  = d ? r_wih : f_wih;
    const float* whh  = d ? r_whh : f_whh;
    const float* bihp = d ? r_bih : f_bih;
    const float* bhhp = d ? r_bhh : f_bhh;

    for (int i = threadIdx.x; i < 128 * 16; i += blockDim.x) {
        int g = i >> 4, j = i & 15;
        s_wih[j][g] = wih[i];
    }
    for (int i = threadIdx.x; i < 128 * 32; i += blockDim.x) {
        int g = i >> 5, j = i & 31;
        s_whh[j][g] = whh[i];
    }
    if (threadIdx.x < 128) s_b[threadIdx.x] = bihp[threadIdx.x] + bhhp[threadIdx.x];
    __syncthreads();

    const int warp = threadIdx.x >> 5;
    const int lane = threadIdx.x & 31;
    const int n = blockIdx.x * 8 + warp;

    const float* beats = out;
    float* bars = out + BARS_OUT_OFF;

    float h = 0.0f, c = 0.0f;
    for (int s = 0; s < 4; s++) {
        int t = d ? (3 - s) : s;
        float xv = 0.0f;
        if (lane < 16)
            xv = beats[(((size_t)n * 4 + t) * 8 + 7) * 16 + lane];

        float gi = s_b[lane];
        float gf = s_b[32 + lane];
        float gg = s_b[64 + lane];
        float go = s_b[96 + lane];
#pragma unroll
        for (int j = 0; j < 16; j++) {
            float xj = __shfl_sync(0xffffffffu, xv, j);
            gi = fmaf(s_wih[j][lane],      xj, gi);
            gf = fmaf(s_wih[j][32 + lane], xj, gf);
            gg = fmaf(s_wih[j][64 + lane], xj, gg);
            go = fmaf(s_wih[j][96 + lane], xj, go);
        }
#pragma unroll
        for (int j = 0; j < 32; j++) {
            float hj = __shfl_sync(0xffffffffu, h, j);
            gi = fmaf(s_whh[j][lane],      hj, gi);
            gf = fmaf(s_whh[j][32 + lane], hj, gf);
            gg = fmaf(s_whh[j][64 + lane], hj, gg);
            go = fmaf(s_whh[j][96 + lane], hj, go);
        }
        c = fmaf(sig_(gf), c, sig_(gi) * tanha_(gg));
        h = sig_(go) * tanha_(c);
        bars[((size_t)n * 4 + t) * 64 + d * 32 + lane] = h;
    }
}

// ---------------- launch ----------------------------------------------------
extern "C" void kernel_launch(void* const* d_in, const int* in_sizes, int n_in,
                              void* d_out, int out_size) {
    const float* channels = (const float*)d_in[0];
    const float* lin_w    = (const float*)d_in[1];
    const float* lin_b    = (const float*)d_in[2];
    const float* b_wih    = (const float*)d_in[3];
    const float* b_whh    = (const float*)d_in[4];
    const float* b_bih    = (const float*)d_in[5];
    const float* b_bhh    = (const float*)d_in[6];
    const float* f_wih    = (const float*)d_in[7];
    const float* f_whh    = (const float*)d_in[8];
    const float* f_bih    = (const float*)d_in[9];
    const float* f_bhh    = (const float*)d_in[10];
    const float* r_wih    = (const float*)d_in[11];
    const float* r_whh    = (const float*)d_in[12];
    const float* r_bih    = (const float*)d_in[13];
    const float* r_bhh    = (const float*)d_in[14];
    float* out = (float*)d_out;

    int prep_n = 128 * KPAD + 64 * K2PAD + 64;
    prep_kernel<<<(prep_n + 255) / 256, 256>>>(lin_w, b_wih, b_bih, b_bhh);
    gemm1_kernel<<<NROWS / 128, 256>>>(channels, lin_b);
    gemm2_beats<<<NROWS / 128, 256>>>(b_whh, out);
    dim3 g4(NSEQ_R / 8, 2);
    bars_kernel<<<g4, 256>>>(f_wih, f_whh, f_bih, f_bhh,
                             r_wih, r_whh, r_bih, r_bhh, out);
}

// round 10
// speedup vs baseline: 5.7298x; 1.0871x over previous
#include <cuda_runtime.h>
#include <cuda_bf16.h>
#include <cuda_fp16.h>
#include <cstdint>

// ---------------- problem constants ----------------
#define NROWS   32768        // B*BARS*BEATS*FRAC
#define KF      940          // input features (10*2*47)
#define KPAD    960          // K padded to 30 x 32
#define NOUT    100          // linear out
#define K2PAD   112          // padded K for gemm2 (7 x 16)
#define NSEQ_R  1024         // bars LSTM sequences
#define BEATS_OUT_ELEMS (32768 * 16)
#define BARS_OUT_OFF    BEATS_OUT_ELEMS
#define SSTR    40           // smem row stride in b16 elems (80B, 16B-aligned)
#define ARR_ELEMS (128 * SSTR)   // 5120 elems per array
#define XGS     66           // fused-kernel smem row stride (floats, even)

typedef unsigned int u32;

// ---------------- scratch ----------------
__device__ __half g_Whf[128 * KPAD];     // linear weight fp16 (permuted)
__device__ __half g_Wbh[64 * K2PAD];     // beats wih fp16 (padded)
__device__ float g_gb[64];
// Xlin as fp16, row stride K2PAD; pad cols [100,112) never written -> stay 0
__device__ __half g_Xh[(size_t)NROWS * K2PAD];

// ---------------- fast activations ----------------
__device__ __forceinline__ float tanha_(float x) {
    float y;
    asm("tanh.approx.f32 %0, %1;" : "=f"(y) : "f"(x));
    return y;
}
__device__ __forceinline__ float sig_(float x) {
    return fmaf(tanha_(0.5f * x), 0.5f, 0.5f);
}

// ---------------- K0: permute weights (fp16), beats weights ---------------
__global__ void prep_kernel(const float* __restrict__ lin_w,
                            const float* __restrict__ b_wih,
                            const float* __restrict__ b_bih,
                            const float* __restrict__ b_bhh) {
    int idx = blockIdx.x * blockDim.x + threadIdx.x;
    if (idx < 128 * KPAD) {
        int o = idx / KPAD;
        int m = idx % KPAD;
        float v = 0.0f;
        if (o < NOUT && m < KF) {
            int c10 = m / 94;
            int r   = m % 94;
            int c2  = r / 47;
            int c47 = r % 47;
            v = lin_w[o * KF + c10 * 94 + c47 * 2 + c2];
        }
        g_Whf[idx] = __float2half_rn(v);
    } else if (idx < 128 * KPAD + 64 * K2PAD) {
        int j = idx - 128 * KPAD;
        int n = j / K2PAD;
        int k = j % K2PAD;
        float v = (k < NOUT) ? b_wih[n * NOUT + k] : 0.0f;
        g_Wbh[j] = __float2half_rn(v);
    } else if (idx < 128 * KPAD + 64 * K2PAD + 64) {
        int j = idx - 128 * KPAD - 64 * K2PAD;
        g_gb[j] = b_bih[j] + b_bhh[j];
    }
}

// ---------------- mma helpers ----------------
__device__ __forceinline__ void ldsm4(u32& r0, u32& r1, u32& r2, u32& r3,
                                      u32 addr) {
    asm volatile("ldmatrix.sync.aligned.m8n8.x4.shared.b16 {%0,%1,%2,%3},[%4];"
                 : "=r"(r0), "=r"(r1), "=r"(r2), "=r"(r3) : "r"(addr));
}
__device__ __forceinline__ void ldsm2(u32& r0, u32& r1, u32 addr) {
    asm volatile("ldmatrix.sync.aligned.m8n8.x2.shared.b16 {%0,%1},[%2];"
                 : "=r"(r0), "=r"(r1) : "r"(addr));
}
__device__ __forceinline__ void mma_f16(float* c, const u32* a, const u32* b) {
    asm volatile(
        "mma.sync.aligned.m16n8k16.row.col.f32.f16.f16.f32 "
        "{%0,%1,%2,%3},{%4,%5,%6,%7},{%8,%9},{%0,%1,%2,%3};"
        : "+f"(c[0]), "+f"(c[1]), "+f"(c[2]), "+f"(c[3])
        : "r"(a[0]), "r"(a[1]), "r"(a[2]), "r"(a[3]), "r"(b[0]), "r"(b[1]));
}

// Register staging for the double-buffer prefetch in gemm1.
struct TileRegs {
    float x[16];
    uint4 wh[2];
};

__device__ __forceinline__ void load_tile(int K0, int lc,
                                          const float* __restrict__ xrow,
                                          const __half* __restrict__ wrow,
                                          TileRegs& t) {
#pragma unroll
    for (int j = 0; j < 4; j++) {
        int kb = K0 + lc + j * 4;
        if (kb + 3 < KF) {
            float4 v = *(const float4*)(xrow + K0 + j * 4);
            t.x[j * 4 + 0] = v.x; t.x[j * 4 + 1] = v.y;
            t.x[j * 4 + 2] = v.z; t.x[j * 4 + 3] = v.w;
        } else {
#pragma unroll
            for (int e = 0; e < 4; e++)
                t.x[j * 4 + e] = (kb + e < KF) ? xrow[K0 + j * 4 + e] : 0.0f;
        }
    }
    t.wh[0] = *(const uint4*)(wrow + K0);
    t.wh[1] = *(const uint4*)(wrow + K0 + 8);
}

__device__ __forceinline__ void store_tile(__half* bufbase, int off,
                                           const TileRegs& t) {
    __half* xp = bufbase + off;
    __half* wp = bufbase + ARR_ELEMS + off;
#pragma unroll
    for (int p = 0; p < 8; p++) {
        __half2 h = __floats2half2_rn(t.x[2 * p], t.x[2 * p + 1]);
        *(__half2*)(xp + 2 * p) = h;
    }
    *(uint4*)wp       = t.wh[0];
    *(uint4*)(wp + 8) = t.wh[1];
}

// ---------------- K1: Xlin = relu(X @ W^T + b), single-pass fp16 mma -------
// 4x2 warp grid: wm=w&3 (32 rows), wn=w>>2 (64 cols; wn1 trims to 5 nf).
// Balanced: each SMSP gets one full-N and one trimmed warp.
__global__ __launch_bounds__(256, 2)
void gemm1_kernel(const float* __restrict__ X, const float* __restrict__ lin_b) {
    __shared__ __align__(16) __half smem[2 * 2 * ARR_ELEMS];   // 40 KB

    const int tid  = threadIdx.x;
    const int row0 = blockIdx.x * 128;
    const int lr   = tid >> 1;        // 0..127 loader row
    const int lc   = (tid & 1) * 16;  // 0 / 16 loader col base
    const int soff = lr * SSTR + lc;

    const float* xrow = X + (size_t)(row0 + lr) * KF + lc;
    const __half* wrow = g_Whf + lr * KPAD + lc;

    // ldmatrix lane geometry
    const int lane = tid & 31;
    const int w    = tid >> 5;
    const int wm   = w & 3;       // 0..3 -> 32-row quarter
    const int wn   = w >> 2;      // 0..1 -> 64-col half
    const int NF   = wn ? 5 : 8;  // wn1: cols 64..103 only
    const int dra  = ((lane >> 3) & 1) * 8 + (lane & 7);
    const int dca  = (lane >> 4) * 8;
    const int aoff = (wm * 32 + dra) * SSTR + dca;   // + mf*16*SSTR + kf
    const int l2   = lane & 15;
    const int boff = (wn * 64 + (l2 & 7)) * SSTR + (l2 >> 3) * 8;  // + nf*8*SSTR

    const u32 sbase = (u32)__cvta_generic_to_shared(smem);

    float acc[2][8][4];
#pragma unroll
    for (int a = 0; a < 2; a++)
#pragma unroll
        for (int b = 0; b < 8; b++)
#pragma unroll
            for (int c = 0; c < 4; c++) acc[a][b][c] = 0.0f;

    TileRegs t;
    load_tile(0, lc, xrow, wrow, t);
    store_tile(smem, soff, t);
    load_tile(32, lc, xrow, wrow, t);
    __syncthreads();

    for (int it = 0; it < 30; ++it) {
        const u32 cb = sbase + (u32)((it & 1) * (2 * ARR_ELEMS * 2));

#pragma unroll
        for (int kf = 0; kf < 32; kf += 16) {
            u32 af[2][4];
            u32 bf[8][2];
#pragma unroll
            for (int mf = 0; mf < 2; mf++) {
                u32 ea = (u32)(aoff + mf * 16 * SSTR + kf) * 2u;
                ldsm4(af[mf][0], af[mf][1], af[mf][2], af[mf][3], cb + ea);
            }
#pragma unroll
            for (int nf = 0; nf < 8; nf++)
                if (nf < NF) {
                    u32 eb = (u32)(boff + nf * 8 * SSTR + kf) * 2u
                             + (u32)(ARR_ELEMS * 2);
                    ldsm2(bf[nf][0], bf[nf][1], cb + eb);
                }
#pragma unroll
            for (int mf = 0; mf < 2; mf++)
#pragma unroll
                for (int nf = 0; nf < 8; nf++)
                    if (nf < NF)
                        mma_f16(acc[mf][nf], af[mf], bf[nf]);
        }

        if (it + 1 < 30) {
            store_tile(smem + ((it + 1) & 1) * (2 * ARR_ELEMS), soff, t);
            if (it + 2 < 30) load_tile((it + 2) * 32, lc, xrow, wrow, t);
            __syncthreads();
        }
    }

    // epilogue: relu + bias, fp16, cols < 100
    const int g  = lane >> 2;
    const int t4 = lane & 3;
#pragma unroll
    for (int mf = 0; mf < 2; mf++)
#pragma unroll
        for (int nf = 0; nf < 8; nf++)
            if (nf < NF) {
                int col = wn * 64 + nf * 8 + t4 * 2;
                if (col < NOUT) {
                    float b0 = __ldg(lin_b + col), b1 = __ldg(lin_b + col + 1);
                    int r1 = row0 + wm * 32 + mf * 16 + g;
                    float v0 = fmaxf(acc[mf][nf][0] + b0, 0.0f);
                    float v1 = fmaxf(acc[mf][nf][1] + b1, 0.0f);
                    float v2 = fmaxf(acc[mf][nf][2] + b0, 0.0f);
                    float v3 = fmaxf(acc[mf][nf][3] + b1, 0.0f);
                    *(__half2*)(g_Xh + (size_t)r1 * K2PAD + col) =
                        __floats2half2_rn(v0, v1);
                    *(__half2*)(g_Xh + (size_t)(r1 + 8) * K2PAD + col) =
                        __floats2half2_rn(v2, v3);
                }
            }
}

// ---------------- K2: fused gates GEMM + beats LSTM ------------------------
// Tile 128 rows = 16 complete sequences. mma phase computes gates into smem,
// then 8 warps run the LSTM, each warp 2 sequences INTERLEAVED.
__global__ __launch_bounds__(256)
void gemm2_beats(const float* __restrict__ whh, float* __restrict__ out) {
    __shared__ float sXG[128 * XGS];   // 33.8 KB

    const int tid  = threadIdx.x;
    const int lane = tid & 31;
    const int w    = tid >> 5;
    const int wm   = w & 3;
    const int wn   = w >> 2;
    const int g    = lane >> 2;
    const int t4   = lane & 3;
    const int rloc = wm * 32;
    const int row0 = blockIdx.x * 128 + rloc;

    float acc[2][4][4];
#pragma unroll
    for (int a = 0; a < 2; a++)
#pragma unroll
        for (int b = 0; b < 4; b++)
#pragma unroll
            for (int c = 0; c < 4; c++) acc[a][b][c] = 0.0f;

#pragma unroll
    for (int kc = 0; kc < 7; kc++) {
        const int k0 = kc * 16 + t4 * 2;
        u32 af[2][4], bf[4][2];
#pragma unroll
        for (int mf = 0; mf < 2; mf++) {
            size_t base = (size_t)(row0 + mf * 16 + g) * K2PAD + k0;
            af[mf][0] = *(const u32*)(g_Xh + base);
            af[mf][1] = *(const u32*)(g_Xh + base + 8 * K2PAD);
            af[mf][2] = *(const u32*)(g_Xh + base + 8);
            af[mf][3] = *(const u32*)(g_Xh + base + 8 * K2PAD + 8);
        }
#pragma unroll
        for (int nf = 0; nf < 4; nf++) {
            int nbase = (wn * 32 + nf * 8 + g) * K2PAD + k0;
            bf[nf][0] = *(const u32*)(g_Wbh + nbase);
            bf[nf][1] = *(const u32*)(g_Wbh + nbase + 8);
        }
#pragma unroll
        for (int mf = 0; mf < 2; mf++)
#pragma unroll
            for (int nf = 0; nf < 4; nf++)
                mma_f16(acc[mf][nf], af[mf], bf[nf]);
    }

    // gates + bias -> smem
#pragma unroll
    for (int mf = 0; mf < 2; mf++)
#pragma unroll
        for (int nf = 0; nf < 4; nf++) {
            int col = wn * 32 + nf * 8 + t4 * 2;
            float b0 = g_gb[col], b1 = g_gb[col + 1];
            int r = rloc + mf * 16 + g;
            *(float2*)(sXG + r * XGS + col) =
                make_float2(acc[mf][nf][0] + b0, acc[mf][nf][1] + b1);
            *(float2*)(sXG + (r + 8) * XGS + col) =
                make_float2(acc[mf][nf][2] + b0, acc[mf][nf][3] + b1);
        }
    __syncthreads();

    // ---- beats LSTM: warp w handles local seqs 2w, 2w+1 interleaved ----
    float w0[16], w1[16];
#pragma unroll
    for (int j = 0; j < 16; j++) {
        w0[j] = whh[lane * 16 + j];
        w1[j] = whh[(lane + 32) * 16 + j];
    }
    const bool lo = lane < 16;

    const int sl0 = w * 2, sl1 = w * 2 + 1;
    float pa0[8], pb0[8], pa1[8], pb1[8];
#pragma unroll
    for (int t = 0; t < 8; t++) {
        pa0[t] = sXG[(sl0 * 8 + t) * XGS + lane];
        pb0[t] = sXG[(sl0 * 8 + t) * XGS + lane + 32];
        pa1[t] = sXG[(sl1 * 8 + t) * XGS + lane];
        pb1[t] = sXG[(sl1 * 8 + t) * XGS + lane + 32];
    }
    float h0 = 0.0f, c0 = 0.0f, h1 = 0.0f, c1 = 0.0f;
    float* ob0 = out + ((size_t)blockIdx.x * 16 + sl0) * 128;
    float* ob1 = out + ((size_t)blockIdx.x * 16 + sl1) * 128;

#pragma unroll
    for (int t = 0; t < 8; t++) {
        float ga0 = pa0[t], gb0 = pb0[t];
        float ga1 = pa1[t], gb1 = pb1[t];
#pragma unroll
        for (int j = 0; j < 16; j++) {
            float hj0 = __shfl_sync(0xffffffffu, h0, j);
            float hj1 = __shfl_sync(0xffffffffu, h1, j);
            ga0 = fmaf(w0[j], hj0, ga0);
            gb0 = fmaf(w1[j], hj0, gb0);
            ga1 = fmaf(w0[j], hj1, ga1);
            gb1 = fmaf(w1[j], hj1, gb1);
        }
        float A0, B0, A1, B1;
        if (lo) {
            A0 = sig_(ga0) * tanha_(gb0);  B0 = 0.0f;
            A1 = sig_(ga1) * tanha_(gb1);  B1 = 0.0f;
        } else {
            A0 = sig_(ga0);  B0 = sig_(gb0);
            A1 = sig_(ga1);  B1 = sig_(gb1);
        }
        float f0 = __shfl_sync(0xffffffffu, A0, lane + 16);
        float o0 = __shfl_sync(0xffffffffu, B0, lane + 16);
        float f1 = __shfl_sync(0xffffffffu, A1, lane + 16);
        float o1 = __shfl_sync(0xffffffffu, B1, lane + 16);
        if (lo) {
            c0 = fmaf(f0, c0, A0);
            h0 = o0 * tanha_(c0);
            ob0[t * 16 + lane] = h0;
            c1 = fmaf(f1, c1, A1);
            h1 = o1 * tanha_(c1);
            ob1[t * 16 + lane] = h1;
        }
    }
}

// ---------------- K3: bars bidirectional LSTM, 2 seqs per warp -------------
__global__ __launch_bounds__(256)
void bars_kernel(const float* __restrict__ f_wih,
                 const float* __restrict__ f_whh,
                 const float* __restrict__ f_bih,
                 const float* __restrict__ f_bhh,
                 const float* __restrict__ r_wih,
                 const float* __restrict__ r_whh,
                 const float* __restrict__ r_bih,
                 const float* __restrict__ r_bhh,
                 float* __restrict__ out) {
    __shared__ float s_wih[16][128];
    __shared__ float s_whh[32][128];
    __shared__ float s_b[128];

    const int d = blockIdx.y;
    const float* wih  = d ? r_wih : f_wih;
    const float* whh  = d ? r_whh : f_whh;
    const float* bihp = d ? r_bih : f_bih;
    const float* bhhp = d ? r_bhh : f_bhh;

    for (int i = threadIdx.x; i < 128 * 16; i += blockDim.x) {
        int g = i >> 4, j = i & 15;
        s_wih[j][g] = wih[i];
    }
    for (int i = threadIdx.x; i < 128 * 32; i += blockDim.x) {
        int g = i >> 5, j = i & 31;
        s_whh[j][g] = whh[i];
    }
    if (threadIdx.x < 128) s_b[threadIdx.x] = bihp[threadIdx.x] + bhhp[threadIdx.x];
    __syncthreads();

    const int warp = threadIdx.x >> 5;
    const int lane = threadIdx.x & 31;
    const int n0 = (blockIdx.x * 8 + warp) * 2;   // two seqs per warp
    const int n1 = n0 + 1;

    const float* beats = out;
    float* bars = out + BARS_OUT_OFF;

    // prefetch beat inputs for all 4 timesteps, both seqs
    float xq0[4], xq1[4];
#pragma unroll
    for (int t = 0; t < 4; t++) {
        xq0[t] = (lane < 16)
            ? beats[(((size_t)n0 * 4 + t) * 8 + 7) * 16 + lane] : 0.0f;
        xq1[t] = (lane < 16)
            ? beats[(((size_t)n1 * 4 + t) * 8 + 7) * 16 + lane] : 0.0f;
    }

    float h0 = 0.0f, c0 = 0.0f, h1 = 0.0f, c1 = 0.0f;
#pragma unroll
    for (int s = 0; s < 4; s++) {
        int t = d ? (3 - s) : s;
        float xv0 = xq0[t], xv1 = xq1[t];

        float gi0 = s_b[lane],      gi1 = gi0;
        float gf0 = s_b[32 + lane], gf1 = gf0;
        float gg0 = s_b[64 + lane], gg1 = gg0;
        float go0 = s_b[96 + lane], go1 = go0;
#pragma unroll
        for (int j = 0; j < 16; j++) {
            float xj0 = __shfl_sync(0xffffffffu, xv0, j);
            float xj1 = __shfl_sync(0xffffffffu, xv1, j);
            float wi = s_wih[j][lane];
            float wf = s_wih[j][32 + lane];
            float wg = s_wih[j][64 + lane];
            float wo = s_wih[j][96 + lane];
            gi0 = fmaf(wi, xj0, gi0);  gi1 = fmaf(wi, xj1, gi1);
            gf0 = fmaf(wf, xj0, gf0);  gf1 = fmaf(wf, xj1, gf1);
            gg0 = fmaf(wg, xj0, gg0);  gg1 = fmaf(wg, xj1, gg1);
            go0 = fmaf(wo, xj0, go0);  go1 = fmaf(wo, xj1, go1);
        }
#pragma unroll
        for (int j = 0; j < 32; j++) {
            float hj0 = __shfl_sync(0xffffffffu, h0, j);
            float hj1 = __shfl_sync(0xffffffffu, h1, j);
            float wi = s_whh[j][lane];
            float wf = s_whh[j][32 + lane];
            float wg = s_whh[j][64 + lane];
            float wo = s_whh[j][96 + lane];
            gi0 = fmaf(wi, hj0, gi0);  gi1 = fmaf(wi, hj1, gi1);
            gf0 = fmaf(wf, hj0, gf0);  gf1 = fmaf(wf, hj1, gf1);
            gg0 = fmaf(wg, hj0, gg0);  gg1 = fmaf(wg, hj1, gg1);
            go0 = fmaf(wo, hj0, go0);  go1 = fmaf(wo, hj1, go1);
        }
        c0 = fmaf(sig_(gf0), c0, sig_(gi0) * tanha_(gg0));
        h0 = sig_(go0) * tanha_(c0);
        c1 = fmaf(sig_(gf1), c1, sig_(gi1) * tanha_(gg1));
        h1 = sig_(go1) * tanha_(c1);
        bars[((size_t)n0 * 4 + t) * 64 + d * 32 + lane] = h0;
        bars[((size_t)n1 * 4 + t) * 64 + d * 32 + lane] = h1;
    }
}

// ---------------- launch ----------------------------------------------------
extern "C" void kernel_launch(void* const* d_in, const int* in_sizes, int n_in,
                              void* d_out, int out_size) {
    const float* channels = (const float*)d_in[0];
    const float* lin_w    = (const float*)d_in[1];
    const float* lin_b    = (const float*)d_in[2];
    const float* b_wih    = (const float*)d_in[3];
    const float* b_whh    = (const float*)d_in[4];
    const float* b_bih    = (const float*)d_in[5];
    const float* b_bhh    = (const float*)d_in[6];
    const float* f_wih    = (const float*)d_in[7];
    const float* f_whh    = (const float*)d_in[8];
    const float* f_bih    = (const float*)d_in[9];
    const float* f_bhh    = (const float*)d_in[10];
    const float* r_wih    = (const float*)d_in[11];
    const float* r_whh    = (const float*)d_in[12];
    const float* r_bih    = (const float*)d_in[13];
    const float* r_bhh    = (const float*)d_in[14];
    float* out = (float*)d_out;

    int prep_n = 128 * KPAD + 64 * K2PAD + 64;
    prep_kernel<<<(prep_n + 255) / 256, 256>>>(lin_w, b_wih, b_bih, b_bhh);
    gemm1_kernel<<<NROWS / 128, 256>>>(channels, lin_b);
    gemm2_beats<<<NROWS / 128, 256>>>(b_whh, out);
    dim3 g4(NSEQ_R / 16, 2);
    bars_kernel<<<g4, 256>>>(f_wih, f_whh, f_bih, f_bhh,
                             r_wih, r_whh, r_bih, r_bhh, out);
}